// round 11
// baseline (speedup 1.0000x reference)
#include <cuda_runtime.h>
#include <math.h>

#define NPT 3000
#define NPAD 3008
#define CDIM 128
#define BB 2
#define NLAYERS 6
#define FEAT_SZ (BB*CDIM*NPT)

// ---------------- scratch (device globals; no allocations allowed) ----------------
__device__ float g_x[FEAT_SZ];
__device__ float g_tmp[FEAT_SZ];
__device__ float g_q[FEAT_SZ];
__device__ float g_k[FEAT_SZ];
__device__ float g_v[FEAT_SZ];
__device__ float g_msg[FEAT_SZ];
__device__ float g_h1[BB*64*NPT];
__device__ float g_h2[BB*64*NPT];
__device__ float g_ss[4*CDIM];
__device__ float g_S[(size_t)BB * NPAD * NPAD];   // attention logits / probs (72.4 MB)
__device__ float g_rowmax[BB * NPAD];
__device__ double g_rowsum[BB * NPAD];

// ---- compensated accumulation: TwoSum fold of p into (hi, lo). fp32-only. ----
__device__ __forceinline__ void ts_fold(float& hi, float& lo, float p) {
    float t = __fadd_rn(hi, p);
    float z = __fsub_rn(t, hi);
    float e = __fadd_rn(__fsub_rn(hi, __fsub_rn(t, z)), __fsub_rn(p, z));
    lo = __fadd_rn(lo, e);
    hi = t;
}

// ---- ~1-ulp fp32 exp, immune to fast-math (explicit rn intrinsics) ----
__device__ __forceinline__ float exp_rn(float x) {
    if (x < -87.336544f) return 0.0f;
    float kf = rintf(__fmul_rn(x, 1.4426950408889634f));
    float r = __fmaf_rn(-kf, 0.693359375f, x);
    r = __fmaf_rn(-kf, -2.12194440e-4f, r);
    float z = 1.9875691500e-4f;
    z = __fmaf_rn(z, r, 1.3981999507e-3f);
    z = __fmaf_rn(z, r, 8.3334519073e-3f);
    z = __fmaf_rn(z, r, 4.1665795894e-2f);
    z = __fmaf_rn(z, r, 1.6666665459e-1f);
    z = __fmaf_rn(z, r, 5.0000001201e-1f);
    float rr = __fmul_rn(r, r);
    float e = __fadd_rn(__fmaf_rn(z, rr, r), 1.0f);
    int k = (int)kf;
    float s = __int_as_float((k + 127) << 23);  // k in [-126, ~2] here
    return __fmul_rn(e, s);
}

// BN transform: t=(x-m); t*=g; result = fma(t, ri, beta)
__device__ __forceinline__ float bn_xform(float x, float m, float g, float ri, float be) {
    float t = __fsub_rn(x, m);
    t = __fmul_rn(g, t);
    return __fmaf_rn(t, ri, be);
}

// ---------------- init embedding (TwoProd-Kahan over 6 terms) ----------------
__global__ void init_embed_kernel(const float* __restrict__ corr,
                                  const float* __restrict__ W,
                                  const float* __restrict__ bias,
                                  float* __restrict__ out) {
    int idx = blockIdx.x * blockDim.x + threadIdx.x;
    if (idx >= FEAT_SZ) return;
    int n = idx % NPT;
    int c = (idx / NPT) % CDIM;
    int b = idx / (CDIM * NPT);
    const float* cp = corr + (b * NPT + n) * 6;
    float hi = 0.f, lo = 0.f;
#pragma unroll
    for (int k = 0; k < 6; k++) {
        float a = W[c * 6 + k], bb = cp[k];
        float p = __fmul_rn(a, bb);
        float e = __fmaf_rn(a, bb, -p);
        ts_fold(hi, lo, p);
        lo = __fadd_rn(lo, e);
    }
    out[idx] = __fadd_rn(__fadd_rn(hi, lo), bias[c]);
}

// ---------------- pointwise conv with per-16-chunk compensated folds -----------------
__global__ __launch_bounds__(256) void conv_kernel(
    const float* __restrict__ in, const float* __restrict__ W,
    const float* __restrict__ bias, float* __restrict__ out,
    const float* __restrict__ ss, int relu, int Cout, int Cin) {
    __shared__ float Ws[16 * 68];
    __shared__ float Is[16 * 68];
    int b = blockIdx.z;
    int o0 = blockIdx.y * 64;
    int p0 = blockIdx.x * 64;
    int t = threadIdx.x;
    int to = t >> 4, tp = t & 15;
    float hi[4][4], lo[4][4];
#pragma unroll
    for (int i = 0; i < 4; i++)
#pragma unroll
        for (int j = 0; j < 4; j++) { hi[i][j] = 0.f; lo[i][j] = 0.f; }

    for (int c0 = 0; c0 < Cin; c0 += 16) {
        __syncthreads();
        {   // W tile -> Ws[cc][oo] (transposed)
            int oo = t >> 2, cg = (t & 3) << 2;
            int o = o0 + oo;
            float4 w = make_float4(0.f, 0.f, 0.f, 0.f);
            if (o < Cout) w = *(const float4*)(W + o * Cin + c0 + cg);
            Ws[(cg + 0) * 68 + oo] = w.x;
            Ws[(cg + 1) * 68 + oo] = w.y;
            Ws[(cg + 2) * 68 + oo] = w.z;
            Ws[(cg + 3) * 68 + oo] = w.w;
        }
        {   // input tile with optional BN(+relu) transform
            int cc = t >> 4, pg = (t & 15) << 2;
            int c = c0 + cc;
            int p = p0 + pg;
            float4 v = make_float4(0.f, 0.f, 0.f, 0.f);
            if (p < NPT) v = *(const float4*)(in + (b * Cin + c) * NPT + p);
            if (ss) {
                float m = ss[4 * c], g = ss[4 * c + 1], ri = ss[4 * c + 2], be = ss[4 * c + 3];
                v.x = bn_xform(v.x, m, g, ri, be);
                v.y = bn_xform(v.y, m, g, ri, be);
                v.z = bn_xform(v.z, m, g, ri, be);
                v.w = bn_xform(v.w, m, g, ri, be);
            }
            if (relu) {
                v.x = fmaxf(v.x, 0.f); v.y = fmaxf(v.y, 0.f);
                v.z = fmaxf(v.z, 0.f); v.w = fmaxf(v.w, 0.f);
            }
            *(float4*)(Is + cc * 68 + pg) = v;
        }
        __syncthreads();
        float acc[4][4];
#pragma unroll
        for (int i = 0; i < 4; i++)
#pragma unroll
            for (int j = 0; j < 4; j++) acc[i][j] = 0.f;
#pragma unroll
        for (int cc = 0; cc < 16; cc++) {
            float4 a = *(const float4*)(Ws + cc * 68 + 4 * to);
            float4 bb = *(const float4*)(Is + cc * 68 + 4 * tp);
            float av[4] = {a.x, a.y, a.z, a.w};
            float bv[4] = {bb.x, bb.y, bb.z, bb.w};
#pragma unroll
            for (int i = 0; i < 4; i++)
#pragma unroll
                for (int j = 0; j < 4; j++) acc[i][j] += av[i] * bv[j];
        }
#pragma unroll
        for (int i = 0; i < 4; i++)
#pragma unroll
            for (int j = 0; j < 4; j++) ts_fold(hi[i][j], lo[i][j], acc[i][j]);
    }
    int p = p0 + 4 * tp;
    if (p < NPT) {
#pragma unroll
        for (int i = 0; i < 4; i++) {
            int o = o0 + 4 * to + i;
            if (o < Cout) {
                float bi = bias[o];
                float4 r;
                r.x = __fadd_rn(__fadd_rn(hi[i][0], lo[i][0]), bi);
                r.y = __fadd_rn(__fadd_rn(hi[i][1], lo[i][1]), bi);
                r.z = __fadd_rn(__fadd_rn(hi[i][2], lo[i][2]), bi);
                r.w = __fadd_rn(__fadd_rn(hi[i][3], lo[i][3]), bi);
                *(float4*)(out + (b * Cout + o) * NPT + p) = r;
            }
        }
    }
}

// ---------------- BN batch stats (compensated fp32, double finals) ------------------
__global__ void bn_stats_kernel(const float* __restrict__ x, const float* __restrict__ g,
                                const float* __restrict__ beta, float* __restrict__ ss, int Cc) {
    __shared__ float shi[256], slo[256], qhi[256], qlo[256];
    int o = blockIdx.x;
    int t = threadIdx.x;
    const float* p0 = x + o * NPT;
    const float* p1 = x + (Cc + o) * NPT;
    float hs = 0.f, ls = 0.f, hq = 0.f, lq = 0.f;
    for (int i = t; i < NPT; i += 256) {
        float v = p0[i];
        ts_fold(hs, ls, v);
        float p = __fmul_rn(v, v);
        float e = __fmaf_rn(v, v, -p);
        ts_fold(hq, lq, p);
        lq = __fadd_rn(lq, e);
        float w = p1[i];
        ts_fold(hs, ls, w);
        p = __fmul_rn(w, w);
        e = __fmaf_rn(w, w, -p);
        ts_fold(hq, lq, p);
        lq = __fadd_rn(lq, e);
    }
    shi[t] = hs; slo[t] = ls; qhi[t] = hq; qlo[t] = lq;
    __syncthreads();
    for (int off = 128; off > 0; off >>= 1) {
        if (t < off) {
            float h2 = shi[t], l2 = slo[t];
            ts_fold(h2, l2, shi[t + off]);
            l2 = __fadd_rn(l2, slo[t + off]);
            shi[t] = h2; slo[t] = l2;
            h2 = qhi[t]; l2 = qlo[t];
            ts_fold(h2, l2, qhi[t + off]);
            l2 = __fadd_rn(l2, qlo[t + off]);
            qhi[t] = h2; qlo[t] = l2;
        }
        __syncthreads();
    }
    if (t == 0) {
        double mean = ((double)shi[0] + (double)slo[0]) * (1.0 / 6000.0);
        double msq = ((double)qhi[0] + (double)qlo[0]) * (1.0 / 6000.0);
        double var = msq - mean * mean;
        ss[4 * o + 0] = (float)mean;
        ss[4 * o + 1] = g[o];
        ss[4 * o + 2] = (float)(1.0 / sqrt(var + 1e-5));
        ss[4 * o + 3] = beta[o];
    }
}

__global__ void bn_apply_relu_kernel(const float* __restrict__ x, const float* __restrict__ ss,
                                     float* __restrict__ y, int Cc, int total) {
    int idx = blockIdx.x * 256 + threadIdx.x;
    if (idx >= total) return;
    int c = (idx / NPT) % Cc;
    float v = bn_xform(x[idx], ss[4 * c], ss[4 * c + 1], ss[4 * c + 2], ss[4 * c + 3]);
    y[idx] = fmaxf(v, 0.f);
}

__global__ void add_kernel(float* __restrict__ x, const float* __restrict__ m, int total) {
    int idx = blockIdx.x * 256 + threadIdx.x;
    if (idx < total) x[idx] = __fadd_rn(x[idx], m[idx]);
}

// ---------------- attention pass 1: logits + row max (compensated dots) ----------------
__global__ __launch_bounds__(256, 1) void attn_logits_kernel(
    const float* __restrict__ Q, const float* __restrict__ K,
    const float* __restrict__ src, const float* __restrict__ tgt,
    float* __restrict__ S, float* __restrict__ rowmax) {
    extern __shared__ float sm[];
    float* Qs = sm;                  // 128*64
    float* Ks = Qs + 128 * 64;       // 128*64
    float* kc = Ks + 128 * 64;       // 64*6

    int b = blockIdx.y;
    int q0 = blockIdx.x * 64;
    int t = threadIdx.x;
    const float SCALE = __fdiv_rn(1.0f, __fsqrt_rn(128.0f));  // ref's rounding chain

    const float* Qb = Q + b * CDIM * NPT;
    const float* Kb = K + b * CDIM * NPT;
    float* Sb = S + (size_t)b * NPAD * NPAD;

#pragma unroll
    for (int r = 0; r < 8; r++) {   // load Q tile [128][64]
        int g = t + 256 * r;
        int c = g >> 4;
        int q4 = (g & 15) << 2;
        float4 v = make_float4(0.f, 0.f, 0.f, 0.f);
        if (q0 + q4 < NPT) v = *(const float4*)(Qb + c * NPT + q0 + q4);
        *(float4*)(Qs + c * 64 + q4) = v;
    }

    int tq = t >> 4, tk = t & 15;        // q=4tq+i, k=4tk+j
    float qsr[4][3], qtg[4][3], rm[4];
#pragma unroll
    for (int i = 0; i < 4; i++) {
        rm[i] = -1e30f;
        int gq = q0 + 4 * tq + i;
        if (gq < NPT) {
#pragma unroll
            for (int k = 0; k < 3; k++) {
                qsr[i][k] = src[(b * NPT + gq) * 3 + k];
                qtg[i][k] = tgt[(b * NPT + gq) * 3 + k];
            }
        } else {
#pragma unroll
            for (int k = 0; k < 3; k++) { qsr[i][k] = 0.f; qtg[i][k] = 0.f; }
        }
    }

    for (int j0 = 0; j0 < NPAD; j0 += 64) {
        __syncthreads();
#pragma unroll
        for (int r = 0; r < 8; r++) {   // K tile
            int g = t + 256 * r;
            int c = g >> 4;
            int j4 = (g & 15) << 2;
            float4 kv = make_float4(0.f, 0.f, 0.f, 0.f);
            if (j0 + j4 < NPT) kv = *(const float4*)(Kb + c * NPT + j0 + j4);
            *(float4*)(Ks + c * 64 + j4) = kv;
        }
        if (t < 64) {
            int gj = j0 + t;
#pragma unroll
            for (int k = 0; k < 3; k++) {
                kc[t * 6 + k]     = (gj < NPT) ? src[(b * NPT + gj) * 3 + k] : 0.f;
                kc[t * 6 + 3 + k] = (gj < NPT) ? tgt[(b * NPT + gj) * 3 + k] : 0.f;
            }
        }
        __syncthreads();

        float dhi[4][4], dlo[4][4];
#pragma unroll
        for (int i = 0; i < 4; i++)
#pragma unroll
            for (int j = 0; j < 4; j++) { dhi[i][j] = 0.f; dlo[i][j] = 0.f; }
#pragma unroll 1
        for (int ch = 0; ch < 8; ch++) {
            float s[4][4];
#pragma unroll
            for (int i = 0; i < 4; i++)
#pragma unroll
                for (int j = 0; j < 4; j++) s[i][j] = 0.f;
#pragma unroll
            for (int cc = 0; cc < 16; cc++) {
                int c = ch * 16 + cc;
                float4 a = *(const float4*)(Qs + c * 64 + 4 * tq);
                float4 bb = *(const float4*)(Ks + c * 64 + 4 * tk);
                float av[4] = {a.x, a.y, a.z, a.w};
                float bv[4] = {bb.x, bb.y, bb.z, bb.w};
#pragma unroll
                for (int i = 0; i < 4; i++)
#pragma unroll
                    for (int j = 0; j < 4; j++) s[i][j] += av[i] * bv[j];
            }
#pragma unroll
            for (int i = 0; i < 4; i++)
#pragma unroll
                for (int j = 0; j < 4; j++) ts_fold(dhi[i][j], dlo[i][j], s[i][j]);
        }
        // spatial compatibility + scale; write logits
#pragma unroll
        for (int i = 0; i < 4; i++) {
            float lg[4];
#pragma unroll
            for (int j = 0; j < 4; j++) {
                int jj = 4 * tk + j;
                int gj = j0 + jj;
                float ks0 = kc[jj * 6], ks1 = kc[jj * 6 + 1], ks2 = kc[jj * 6 + 2];
                float kt0 = kc[jj * 6 + 3], kt1 = kc[jj * 6 + 4], kt2 = kc[jj * 6 + 5];
                float dx = __fsub_rn(qsr[i][0], ks0);
                float dy = __fsub_rn(qsr[i][1], ks1);
                float dz = __fsub_rn(qsr[i][2], ks2);
                float d2s = __fmaf_rn(dz, dz, __fmaf_rn(dy, dy, __fmul_rn(dx, dx)));
                float ds = __fsqrt_rn(d2s);
                dx = __fsub_rn(qtg[i][0], kt0);
                dy = __fsub_rn(qtg[i][1], kt1);
                dz = __fsub_rn(qtg[i][2], kt2);
                float d2t = __fmaf_rn(dz, dz, __fmaf_rn(dy, dy, __fmul_rn(dx, dx)));
                float dt = __fsqrt_rn(d2t);
                float dd = __fsub_rn(ds, dt);
                float sc = fmaxf(__fmaf_rn(-dd, dd, 1.0f), 0.f);
                float dot = __fadd_rn(dhi[i][j], dlo[i][j]);
                float logit = __fmul_rn(sc, __fmul_rn(dot, SCALE));
                if (gj >= NPT) logit = -1e30f;
                lg[j] = logit;
                rm[i] = fmaxf(rm[i], logit);
            }
            *(float4*)(Sb + (size_t)(q0 + 4 * tq + i) * NPAD + j0 + 4 * tk) =
                make_float4(lg[0], lg[1], lg[2], lg[3]);
        }
    }
#pragma unroll
    for (int i = 0; i < 4; i++) {
#pragma unroll
        for (int off = 8; off > 0; off >>= 1)
            rm[i] = fmaxf(rm[i], __shfl_xor_sync(0xffffffffu, rm[i], off));
        if (tk == 0) rowmax[b * NPAD + q0 + 4 * tq + i] = rm[i];
    }
}

// ---------------- attention pass 2: p = exp(S - max) in place; compensated row sum ----
__global__ __launch_bounds__(256) void softmax_rows_kernel(
    float* __restrict__ S, const float* __restrict__ rowmax, double* __restrict__ rowsum) {
    __shared__ float rhi[256], rlo[256];
    int row = blockIdx.x;          // b*NPAD + q
    int t = threadIdx.x;
    float mx = rowmax[row];
    float* Sr = S + (size_t)row * NPAD;
    float hs = 0.f, ls = 0.f;
    for (int i = t; i < NPAD; i += 256) {
        float p = exp_rn(__fsub_rn(Sr[i], mx));
        Sr[i] = p;
        ts_fold(hs, ls, p);
    }
    rhi[t] = hs; rlo[t] = ls;
    __syncthreads();
    for (int off = 128; off > 0; off >>= 1) {
        if (t < off) {
            float h2 = rhi[t], l2 = rlo[t];
            ts_fold(h2, l2, rhi[t + off]);
            l2 = __fadd_rn(l2, rlo[t + off]);
            rhi[t] = h2; rlo[t] = l2;
        }
        __syncthreads();
    }
    if (t == 0) rowsum[row] = (double)rhi[0] + (double)rlo[0];
}

// ---------------- attention pass 3: msg = (sum_j p*V) / rowsum, compensated -----------
__global__ __launch_bounds__(256, 1) void attn_pv_kernel(
    const float* __restrict__ V, const float* __restrict__ S,
    const double* __restrict__ rowsum, float* __restrict__ msg) {
    extern __shared__ float smf[];
    float* rinvf = smf;                        // 64
    float* Vs = rinvf + 64;                    // 128*64
    float* Wt = Vs + 128 * 64;                 // 64*68  (p transposed [j][q])

    int b = blockIdx.y;
    int q0 = blockIdx.x * 64;
    int t = threadIdx.x;
    const float* Vb = V + b * CDIM * NPT;
    const float* Sb = S + (size_t)b * NPAD * NPAD;

    if (t < 64) rinvf[t] = (float)(1.0 / rowsum[b * NPAD + q0 + t]);

    int tc = t >> 4, tq2 = t & 15;             // c=8tc+i, q=4tq2+j
    float Ohi[8][4], Olo[8][4];
#pragma unroll
    for (int i = 0; i < 8; i++)
#pragma unroll
        for (int j = 0; j < 4; j++) { Ohi[i][j] = 0.f; Olo[i][j] = 0.f; }

    int pq = t >> 2, pquad = t & 3;

    for (int j0 = 0; j0 < NPAD; j0 += 64) {
        __syncthreads();
#pragma unroll
        for (int r = 0; r < 8; r++) {          // V tile [128][64]
            int g = t + 256 * r;
            int c = g >> 4;
            int j4 = (g & 15) << 2;
            float4 vv = make_float4(0.f, 0.f, 0.f, 0.f);
            if (j0 + j4 < NPT) vv = *(const float4*)(Vb + c * NPT + j0 + j4);
            *(float4*)(Vs + c * 64 + j4) = vv;
        }
        {   // P tile [64q][64j] -> Wt[j][q] (raw probs)
            const float* Pr = Sb + (size_t)(q0 + pq) * NPAD + j0;
#pragma unroll
            for (int k = 0; k < 4; k++) {
                int jj = pquad * 16 + k * 4;
                float4 p4 = *(const float4*)(Pr + jj);
                Wt[(jj + 0) * 68 + pq] = p4.x;
                Wt[(jj + 1) * 68 + pq] = p4.y;
                Wt[(jj + 2) * 68 + pq] = p4.z;
                Wt[(jj + 3) * 68 + pq] = p4.w;
            }
        }
        __syncthreads();
        float O[8][4];
#pragma unroll
        for (int i = 0; i < 8; i++)
#pragma unroll
            for (int j = 0; j < 4; j++) O[i][j] = 0.f;
#pragma unroll 4
        for (int jt = 0; jt < 64; jt++) {
            float4 w4 = *(const float4*)(Wt + jt * 68 + 4 * tq2);
            float wv[4] = {w4.x, w4.y, w4.z, w4.w};
#pragma unroll
            for (int i = 0; i < 8; i++) {
                float v = Vs[(8 * tc + i) * 64 + jt];
#pragma unroll
                for (int j = 0; j < 4; j++) O[i][j] += v * wv[j];
            }
        }
#pragma unroll
        for (int i = 0; i < 8; i++)
#pragma unroll
            for (int j = 0; j < 4; j++) ts_fold(Ohi[i][j], Olo[i][j], O[i][j]);
    }
    __syncthreads();
    float rv[4];
#pragma unroll
    for (int j = 0; j < 4; j++) rv[j] = rinvf[4 * tq2 + j];
    int gq = q0 + 4 * tq2;
    if (gq < NPT) {
#pragma unroll
        for (int i = 0; i < 8; i++) {
            int c = 8 * tc + i;
            float4 r;
            r.x = __fmaf_rn(Ohi[i][0], rv[0], __fmul_rn(Olo[i][0], rv[0]));
            r.y = __fmaf_rn(Ohi[i][1], rv[1], __fmul_rn(Olo[i][1], rv[1]));
            r.z = __fmaf_rn(Ohi[i][2], rv[2], __fmul_rn(Olo[i][2], rv[2]));
            r.w = __fmaf_rn(Ohi[i][3], rv[3], __fmul_rn(Olo[i][3], rv[3]));
            *(float4*)(msg + (b * CDIM + c) * NPT + gq) = r;
        }
    }
}

// ---------------- final head ----------------
__global__ void conf_kernel(const float* __restrict__ h, const float* __restrict__ w,
                            const float* __restrict__ bias, float* __restrict__ out) {
    int idx = blockIdx.x * 256 + threadIdx.x;
    if (idx >= BB * NPT) return;
    int b = idx / NPT, n = idx % NPT;
    float hi = 0.f, lo = 0.f;
#pragma unroll
    for (int c = 0; c < 32; c++) {
        float a = w[c];
        float v = fmaxf(h[(b * 32 + c) * NPT + n], 0.f);
        float p = __fmul_rn(a, v);
        float e = __fmaf_rn(a, v, -p);
        ts_fold(hi, lo, p);
        lo = __fadd_rn(lo, e);
    }
    out[idx] = __fadd_rn(__fadd_rn(hi, lo), bias[0]);
}

__global__ void norm_kernel(const float* __restrict__ x, float* __restrict__ out) {
    int idx = blockIdx.x * 256 + threadIdx.x;
    if (idx >= BB * NPT) return;
    int b = idx / NPT, n = idx % NPT;
    float hi = 0.f, lo = 0.f;
#pragma unroll 8
    for (int c = 0; c < 128; c++) {
        float v = x[(b * 128 + c) * NPT + n];
        float p = __fmul_rn(v, v);
        float e = __fmaf_rn(v, v, -p);
        ts_fold(hi, lo, p);
        lo = __fadd_rn(lo, e);
    }
    float nf = __fsqrt_rn(__fadd_rn(hi, lo));
    nf = fmaxf(nf, 1e-12f);
#pragma unroll 8
    for (int c = 0; c < 128; c++)
        out[(b * 128 + c) * NPT + n] = __fdiv_rn(x[(b * 128 + c) * NPT + n], nf);
}

// ---------------- host ----------------
extern "C" void kernel_launch(void* const* d_in, const int* in_sizes, int n_in,
                              void* d_out, int out_size) {
    const float* corr   = (const float*)d_in[0];
    const float* src    = (const float*)d_in[1];
    const float* tgt    = (const float*)d_in[2];
    const float* init_W = (const float*)d_in[3];
    const float* init_b = (const float*)d_in[4];
    const float* pcn_W  = (const float*)d_in[5];
    const float* pcn_b  = (const float*)d_in[6];
    const float* pcn_g  = (const float*)d_in[7];
    const float* pcn_be = (const float*)d_in[8];
    const float* qW = (const float*)d_in[9];
    const float* qb = (const float*)d_in[10];
    const float* kW = (const float*)d_in[11];
    const float* kb = (const float*)d_in[12];
    const float* vW = (const float*)d_in[13];
    const float* vb = (const float*)d_in[14];
    const float* m1W = (const float*)d_in[15];
    const float* m1b = (const float*)d_in[16];
    const float* m1g = (const float*)d_in[17];
    const float* m1be = (const float*)d_in[18];
    const float* m2W = (const float*)d_in[19];
    const float* m2b = (const float*)d_in[20];
    const float* m2g = (const float*)d_in[21];
    const float* m2be = (const float*)d_in[22];
    const float* m3W = (const float*)d_in[23];
    const float* m3b = (const float*)d_in[24];
    const float* c1W = (const float*)d_in[25];
    const float* c1b = (const float*)d_in[26];
    const float* c2W = (const float*)d_in[27];
    const float* c2b = (const float*)d_in[28];
    const float* c3W = (const float*)d_in[29];
    const float* c3b = (const float*)d_in[30];
    float* out = (float*)d_out;

    float *x, *tmp, *q, *k, *v, *msg, *h1, *h2, *ss, *S, *rmax;
    double *rsum;
    cudaGetSymbolAddress((void**)&x, g_x);
    cudaGetSymbolAddress((void**)&tmp, g_tmp);
    cudaGetSymbolAddress((void**)&q, g_q);
    cudaGetSymbolAddress((void**)&k, g_k);
    cudaGetSymbolAddress((void**)&v, g_v);
    cudaGetSymbolAddress((void**)&msg, g_msg);
    cudaGetSymbolAddress((void**)&h1, g_h1);
    cudaGetSymbolAddress((void**)&h2, g_h2);
    cudaGetSymbolAddress((void**)&ss, g_ss);
    cudaGetSymbolAddress((void**)&S, g_S);
    cudaGetSymbolAddress((void**)&rmax, g_rowmax);
    cudaGetSymbolAddress((void**)&rsum, g_rowsum);

    size_t smem1 = (size_t)(2 * 128 * 64 + 64 * 6) * sizeof(float);
    size_t smem3 = (size_t)(64 + 128 * 64 + 64 * 68) * sizeof(float);
    cudaFuncSetAttribute(attn_logits_kernel, cudaFuncAttributeMaxDynamicSharedMemorySize,
                         (int)smem1);
    cudaFuncSetAttribute(attn_pv_kernel, cudaFuncAttributeMaxDynamicSharedMemorySize,
                         (int)smem3);

    const int EW = (FEAT_SZ + 255) / 256;
    dim3 cg128(47, 2, BB);   // Cout=128
    dim3 cg64(47, 1, BB);    // Cout<=64

    init_embed_kernel<<<EW, 256>>>(corr, init_W, init_b, x);

    for (int i = 0; i < NLAYERS; i++) {
        conv_kernel<<<cg128, 256>>>(x, pcn_W + i * 128 * 128, pcn_b + i * 128, tmp,
                                    nullptr, 0, 128, 128);
        bn_stats_kernel<<<128, 256>>>(tmp, pcn_g + i * 128, pcn_be + i * 128, ss, 128);
        bn_apply_relu_kernel<<<EW, 256>>>(tmp, ss, x, 128, FEAT_SZ);
        conv_kernel<<<cg128, 256>>>(x, qW + i * 16384, qb + i * 128, q, nullptr, 0, 128, 128);
        conv_kernel<<<cg128, 256>>>(x, kW + i * 16384, kb + i * 128, k, nullptr, 0, 128, 128);
        conv_kernel<<<cg128, 256>>>(x, vW + i * 16384, vb + i * 128, v, nullptr, 0, 128, 128);
        attn_logits_kernel<<<dim3(47, BB), 256, smem1>>>(q, k, src, tgt, S, rmax);
        softmax_rows_kernel<<<BB * NPAD, 256>>>(S, rmax, rsum);
        attn_pv_kernel<<<dim3(47, BB), 256, smem3>>>(v, S, rsum, msg);
        conv_kernel<<<cg64, 256>>>(msg, m1W + i * 64 * 128, m1b + i * 64, h1,
                                   nullptr, 0, 64, 128);
        bn_stats_kernel<<<64, 256>>>(h1, m1g + i * 64, m1be + i * 64, ss, 64);
        conv_kernel<<<cg64, 256>>>(h1, m2W + i * 64 * 64, m2b + i * 64, h2, ss, 1, 64, 64);
        bn_stats_kernel<<<64, 256>>>(h2, m2g + i * 64, m2be + i * 64, ss, 64);
        conv_kernel<<<cg128, 256>>>(h2, m3W + i * 128 * 64, m3b + i * 128, msg, ss, 1, 128, 64);
        add_kernel<<<EW, 256>>>(x, msg, FEAT_SZ);
    }

    conv_kernel<<<cg64, 256>>>(x, c1W, c1b, h1, nullptr, 0, 32, 128);
    conv_kernel<<<cg64, 256>>>(h1, c2W, c2b, h2, nullptr, 1, 32, 32);
    conf_kernel<<<(BB * NPT + 255) / 256, 256>>>(h2, c3W, c3b, out);
    norm_kernel<<<(BB * NPT + 255) / 256, 256>>>(x, out + BB * NPT);
}

// round 12
// speedup vs baseline: 1.4229x; 1.4229x over previous
#include <cuda_runtime.h>
#include <math.h>

#define NPT 3000
#define NPAD 3008
#define CDIM 128
#define BB 2
#define NLAYERS 6
#define FEAT_SZ (BB*CDIM*NPT)
#define JSPLIT 3
#define JCHUNK 1024

// ---------------- scratch (device globals; no allocations allowed) ----------------
__device__ float g_x[FEAT_SZ];
__device__ float g_tmp[FEAT_SZ];
__device__ float g_q[FEAT_SZ];
__device__ float g_k[FEAT_SZ];
__device__ float g_v[FEAT_SZ];
__device__ float g_msg[FEAT_SZ];
__device__ float g_h1[BB*64*NPT];
__device__ float g_h2[BB*64*NPT];
__device__ float g_ss[4*CDIM];
__device__ float g_ss2[4*CDIM];
__device__ float g_S[(size_t)BB * NPAD * NPAD];   // attention logits (72.4 MB)
__device__ float g_rmaxp[JSPLIT*BB*NPAD];
__device__ float g_lhi[JSPLIT*BB*NPAD];
__device__ float g_llo[JSPLIT*BB*NPAD];
__device__ float g_rinv[BB*NPAD];
__device__ float g_opart[(size_t)JSPLIT*FEAT_SZ]; // 9.2 MB

// ---- compensated accumulation: TwoSum fold of p into (hi, lo). fp32-only. ----
__device__ __forceinline__ void ts_fold(float& hi, float& lo, float p) {
    float t = __fadd_rn(hi, p);
    float z = __fsub_rn(t, hi);
    float e = __fadd_rn(__fsub_rn(hi, __fsub_rn(t, z)), __fsub_rn(p, z));
    lo = __fadd_rn(lo, e);
    hi = t;
}

// ---- ~1-ulp fp32 exp, immune to fast-math (explicit rn intrinsics) ----
__device__ __forceinline__ float exp_rn(float x) {
    if (x < -87.336544f) return 0.0f;
    float kf = rintf(__fmul_rn(x, 1.4426950408889634f));
    float r = __fmaf_rn(-kf, 0.693359375f, x);
    r = __fmaf_rn(-kf, -2.12194440e-4f, r);
    float z = 1.9875691500e-4f;
    z = __fmaf_rn(z, r, 1.3981999507e-3f);
    z = __fmaf_rn(z, r, 8.3334519073e-3f);
    z = __fmaf_rn(z, r, 4.1665795894e-2f);
    z = __fmaf_rn(z, r, 1.6666665459e-1f);
    z = __fmaf_rn(z, r, 5.0000001201e-1f);
    float rr = __fmul_rn(r, r);
    float e = __fadd_rn(__fmaf_rn(z, rr, r), 1.0f);
    int k = (int)kf;
    float s = __int_as_float((k + 127) << 23);
    return __fmul_rn(e, s);
}

// BN transform: t=(x-m); t*=g; result = fma(t, ri, beta)
__device__ __forceinline__ float bn_xform(float x, float m, float g, float ri, float be) {
    float t = __fsub_rn(x, m);
    t = __fmul_rn(g, t);
    return __fmaf_rn(t, ri, be);
}

// ---------------- init embedding ----------------
__global__ void init_embed_kernel(const float* __restrict__ corr,
                                  const float* __restrict__ W,
                                  const float* __restrict__ bias,
                                  float* __restrict__ out) {
    int idx = blockIdx.x * blockDim.x + threadIdx.x;
    if (idx >= FEAT_SZ) return;
    int n = idx % NPT;
    int c = (idx / NPT) % CDIM;
    int b = idx / (CDIM * NPT);
    const float* cp = corr + (b * NPT + n) * 6;
    float hi = 0.f, lo = 0.f;
#pragma unroll
    for (int k = 0; k < 6; k++) {
        float a = W[c * 6 + k], bb = cp[k];
        float p = __fmul_rn(a, bb);
        float e = __fmaf_rn(a, bb, -p);
        ts_fold(hi, lo, p);
        lo = __fadd_rn(lo, e);
    }
    out[idx] = __fadd_rn(__fadd_rn(hi, lo), bias[c]);
}

// ---------------- pointwise conv with per-16-chunk compensated folds -----------------
__global__ __launch_bounds__(256) void conv_kernel(
    const float* __restrict__ in, const float* __restrict__ W,
    const float* __restrict__ bias, float* __restrict__ out,
    const float* __restrict__ ss, int relu, int Cout, int Cin) {
    __shared__ float Ws[16 * 68];
    __shared__ float Is[16 * 68];
    int b = blockIdx.z;
    int o0 = blockIdx.y * 64;
    int p0 = blockIdx.x * 64;
    int t = threadIdx.x;
    int to = t >> 4, tp = t & 15;
    float hi[4][4], lo[4][4];
#pragma unroll
    for (int i = 0; i < 4; i++)
#pragma unroll
        for (int j = 0; j < 4; j++) { hi[i][j] = 0.f; lo[i][j] = 0.f; }

    for (int c0 = 0; c0 < Cin; c0 += 16) {
        __syncthreads();
        {
            int oo = t >> 2, cg = (t & 3) << 2;
            int o = o0 + oo;
            float4 w = make_float4(0.f, 0.f, 0.f, 0.f);
            if (o < Cout) w = *(const float4*)(W + o * Cin + c0 + cg);
            Ws[(cg + 0) * 68 + oo] = w.x;
            Ws[(cg + 1) * 68 + oo] = w.y;
            Ws[(cg + 2) * 68 + oo] = w.z;
            Ws[(cg + 3) * 68 + oo] = w.w;
        }
        {
            int cc = t >> 4, pg = (t & 15) << 2;
            int c = c0 + cc;
            int p = p0 + pg;
            float4 v = make_float4(0.f, 0.f, 0.f, 0.f);
            if (p < NPT) v = *(const float4*)(in + (b * Cin + c) * NPT + p);
            if (ss) {
                float m = ss[4 * c], g = ss[4 * c + 1], ri = ss[4 * c + 2], be = ss[4 * c + 3];
                v.x = bn_xform(v.x, m, g, ri, be);
                v.y = bn_xform(v.y, m, g, ri, be);
                v.z = bn_xform(v.z, m, g, ri, be);
                v.w = bn_xform(v.w, m, g, ri, be);
            }
            if (relu) {
                v.x = fmaxf(v.x, 0.f); v.y = fmaxf(v.y, 0.f);
                v.z = fmaxf(v.z, 0.f); v.w = fmaxf(v.w, 0.f);
            }
            *(float4*)(Is + cc * 68 + pg) = v;
        }
        __syncthreads();
        float acc[4][4];
#pragma unroll
        for (int i = 0; i < 4; i++)
#pragma unroll
            for (int j = 0; j < 4; j++) acc[i][j] = 0.f;
#pragma unroll
        for (int cc = 0; cc < 16; cc++) {
            float4 a = *(const float4*)(Ws + cc * 68 + 4 * to);
            float4 bb = *(const float4*)(Is + cc * 68 + 4 * tp);
            float av[4] = {a.x, a.y, a.z, a.w};
            float bv[4] = {bb.x, bb.y, bb.z, bb.w};
#pragma unroll
            for (int i = 0; i < 4; i++)
#pragma unroll
                for (int j = 0; j < 4; j++) acc[i][j] += av[i] * bv[j];
        }
#pragma unroll
        for (int i = 0; i < 4; i++)
#pragma unroll
            for (int j = 0; j < 4; j++) ts_fold(hi[i][j], lo[i][j], acc[i][j]);
    }
    int p = p0 + 4 * tp;
    if (p < NPT) {
#pragma unroll
        for (int i = 0; i < 4; i++) {
            int o = o0 + 4 * to + i;
            if (o < Cout) {
                float bi = bias[o];
                float4 r;
                r.x = __fadd_rn(__fadd_rn(hi[i][0], lo[i][0]), bi);
                r.y = __fadd_rn(__fadd_rn(hi[i][1], lo[i][1]), bi);
                r.z = __fadd_rn(__fadd_rn(hi[i][2], lo[i][2]), bi);
                r.w = __fadd_rn(__fadd_rn(hi[i][3], lo[i][3]), bi);
                *(float4*)(out + (b * Cout + o) * NPT + p) = r;
            }
        }
    }
}

// ---------------- BN batch stats (compensated fp32, double finals) ------------------
__global__ void bn_stats_kernel(const float* __restrict__ x, const float* __restrict__ g,
                                const float* __restrict__ beta, float* __restrict__ ss, int Cc) {
    __shared__ float shi[256], slo[256], qhi[256], qlo[256];
    int o = blockIdx.x;
    int t = threadIdx.x;
    const float* p0 = x + o * NPT;
    const float* p1 = x + (Cc + o) * NPT;
    float hs = 0.f, ls = 0.f, hq = 0.f, lq = 0.f;
    for (int i = t; i < NPT; i += 256) {
        float v = p0[i];
        ts_fold(hs, ls, v);
        float p = __fmul_rn(v, v);
        float e = __fmaf_rn(v, v, -p);
        ts_fold(hq, lq, p);
        lq = __fadd_rn(lq, e);
        float w = p1[i];
        ts_fold(hs, ls, w);
        p = __fmul_rn(w, w);
        e = __fmaf_rn(w, w, -p);
        ts_fold(hq, lq, p);
        lq = __fadd_rn(lq, e);
    }
    shi[t] = hs; slo[t] = ls; qhi[t] = hq; qlo[t] = lq;
    __syncthreads();
    for (int off = 128; off > 0; off >>= 1) {
        if (t < off) {
            float h2 = shi[t], l2 = slo[t];
            ts_fold(h2, l2, shi[t + off]);
            l2 = __fadd_rn(l2, slo[t + off]);
            shi[t] = h2; slo[t] = l2;
            h2 = qhi[t]; l2 = qlo[t];
            ts_fold(h2, l2, qhi[t + off]);
            l2 = __fadd_rn(l2, qlo[t + off]);
            qhi[t] = h2; qlo[t] = l2;
        }
        __syncthreads();
    }
    if (t == 0) {
        double mean = ((double)shi[0] + (double)slo[0]) * (1.0 / 6000.0);
        double msq = ((double)qhi[0] + (double)qlo[0]) * (1.0 / 6000.0);
        double var = msq - mean * mean;
        ss[4 * o + 0] = (float)mean;
        ss[4 * o + 1] = g[o];
        ss[4 * o + 2] = (float)(1.0 / sqrt(var + 1e-5));
        ss[4 * o + 3] = beta[o];
    }
}

// residual with BN fold: x = relu(bn(tmp)) + msg
__global__ void bn_add_kernel(const float* __restrict__ tmp, const float* __restrict__ ss,
                              const float* __restrict__ msg, float* __restrict__ x) {
    int idx = blockIdx.x * 256 + threadIdx.x;
    if (idx >= FEAT_SZ) return;
    int c = (idx / NPT) % CDIM;
    float v = bn_xform(tmp[idx], ss[4 * c], ss[4 * c + 1], ss[4 * c + 2], ss[4 * c + 3]);
    x[idx] = __fadd_rn(fmaxf(v, 0.f), msg[idx]);
}

// ---------------- attention pass 1: logits + per-chunk row max -------------------
__global__ __launch_bounds__(256, 1) void attn_logits_kernel(
    const float* __restrict__ Q, const float* __restrict__ K,
    const float* __restrict__ src, const float* __restrict__ tgt,
    float* __restrict__ S, float* __restrict__ rmaxp) {
    extern __shared__ float sm[];
    float* Qs = sm;                  // 128*64
    float* Ks = Qs + 128 * 64;       // 128*64
    float* kc = Ks + 128 * 64;       // 64*6

    int b = blockIdx.y;
    int jc = blockIdx.z;
    int cb = jc * JCHUNK;
    int ce = min(cb + JCHUNK, NPAD);
    int q0 = blockIdx.x * 64;
    int t = threadIdx.x;
    const float SCALE = __fdiv_rn(1.0f, __fsqrt_rn(128.0f));

    const float* Qb = Q + b * CDIM * NPT;
    const float* Kb = K + b * CDIM * NPT;
    float* Sb = S + (size_t)b * NPAD * NPAD;

#pragma unroll
    for (int r = 0; r < 8; r++) {   // Q tile [128][64]
        int g = t + 256 * r;
        int c = g >> 4;
        int q4 = (g & 15) << 2;
        float4 v = make_float4(0.f, 0.f, 0.f, 0.f);
        if (q0 + q4 < NPT) v = *(const float4*)(Qb + c * NPT + q0 + q4);
        *(float4*)(Qs + c * 64 + q4) = v;
    }

    int tq = t >> 4, tk = t & 15;
    float qsr[4][3], qtg[4][3], rm[4];
#pragma unroll
    for (int i = 0; i < 4; i++) {
        rm[i] = -1e30f;
        int gq = q0 + 4 * tq + i;
        if (gq < NPT) {
#pragma unroll
            for (int k = 0; k < 3; k++) {
                qsr[i][k] = src[(b * NPT + gq) * 3 + k];
                qtg[i][k] = tgt[(b * NPT + gq) * 3 + k];
            }
        } else {
#pragma unroll
            for (int k = 0; k < 3; k++) { qsr[i][k] = 0.f; qtg[i][k] = 0.f; }
        }
    }

    for (int j0 = cb; j0 < ce; j0 += 64) {
        __syncthreads();
#pragma unroll
        for (int r = 0; r < 8; r++) {   // K tile
            int g = t + 256 * r;
            int c = g >> 4;
            int j4 = (g & 15) << 2;
            float4 kv = make_float4(0.f, 0.f, 0.f, 0.f);
            if (j0 + j4 < NPT) kv = *(const float4*)(Kb + c * NPT + j0 + j4);
            *(float4*)(Ks + c * 64 + j4) = kv;
        }
        if (t < 64) {
            int gj = j0 + t;
#pragma unroll
            for (int k = 0; k < 3; k++) {
                kc[t * 6 + k]     = (gj < NPT) ? src[(b * NPT + gj) * 3 + k] : 0.f;
                kc[t * 6 + 3 + k] = (gj < NPT) ? tgt[(b * NPT + gj) * 3 + k] : 0.f;
            }
        }
        __syncthreads();

        float dhi[4][4], dlo[4][4];
#pragma unroll
        for (int i = 0; i < 4; i++)
#pragma unroll
            for (int j = 0; j < 4; j++) { dhi[i][j] = 0.f; dlo[i][j] = 0.f; }
#pragma unroll 1
        for (int ch = 0; ch < 8; ch++) {
            float s[4][4];
#pragma unroll
            for (int i = 0; i < 4; i++)
#pragma unroll
                for (int j = 0; j < 4; j++) s[i][j] = 0.f;
#pragma unroll
            for (int cc = 0; cc < 16; cc++) {
                int c = ch * 16 + cc;
                float4 a = *(const float4*)(Qs + c * 64 + 4 * tq);
                float4 bb = *(const float4*)(Ks + c * 64 + 4 * tk);
                float av[4] = {a.x, a.y, a.z, a.w};
                float bv[4] = {bb.x, bb.y, bb.z, bb.w};
#pragma unroll
                for (int i = 0; i < 4; i++)
#pragma unroll
                    for (int j = 0; j < 4; j++) s[i][j] += av[i] * bv[j];
            }
#pragma unroll
            for (int i = 0; i < 4; i++)
#pragma unroll
                for (int j = 0; j < 4; j++) ts_fold(dhi[i][j], dlo[i][j], s[i][j]);
        }
#pragma unroll
        for (int i = 0; i < 4; i++) {
            float lg[4];
#pragma unroll
            for (int j = 0; j < 4; j++) {
                int jj = 4 * tk + j;
                int gj = j0 + jj;
                float ks0 = kc[jj * 6], ks1 = kc[jj * 6 + 1], ks2 = kc[jj * 6 + 2];
                float kt0 = kc[jj * 6 + 3], kt1 = kc[jj * 6 + 4], kt2 = kc[jj * 6 + 5];
                float dx = __fsub_rn(qsr[i][0], ks0);
                float dy = __fsub_rn(qsr[i][1], ks1);
                float dz = __fsub_rn(qsr[i][2], ks2);
                float d2s = __fmaf_rn(dz, dz, __fmaf_rn(dy, dy, __fmul_rn(dx, dx)));
                float ds = __fsqrt_rn(d2s);
                dx = __fsub_rn(qtg[i][0], kt0);
                dy = __fsub_rn(qtg[i][1], kt1);
                dz = __fsub_rn(qtg[i][2], kt2);
                float d2t = __fmaf_rn(dz, dz, __fmaf_rn(dy, dy, __fmul_rn(dx, dx)));
                float dt = __fsqrt_rn(d2t);
                float dd = __fsub_rn(ds, dt);
                float sc = fmaxf(__fmaf_rn(-dd, dd, 1.0f), 0.f);
                float dot = __fadd_rn(dhi[i][j], dlo[i][j]);
                float logit = __fmul_rn(sc, __fmul_rn(dot, SCALE));
                if (gj >= NPT) logit = -1e30f;
                lg[j] = logit;
                rm[i] = fmaxf(rm[i], logit);
            }
            *(float4*)(Sb + (size_t)(q0 + 4 * tq + i) * NPAD + j0 + 4 * tk) =
                make_float4(lg[0], lg[1], lg[2], lg[3]);
        }
    }
#pragma unroll
    for (int i = 0; i < 4; i++) {
#pragma unroll
        for (int off = 8; off > 0; off >>= 1)
            rm[i] = fmaxf(rm[i], __shfl_xor_sync(0xffffffffu, rm[i], off));
        if (tk == 0) rmaxp[(b * JSPLIT + jc) * NPAD + q0 + 4 * tq + i] = rm[i];
    }
}

// ---------------- attention pass 2 (fused): p=exp(S-max), partial PV + row sums -------
__global__ __launch_bounds__(256, 1) void attn_pv_kernel(
    const float* __restrict__ V, const float* __restrict__ S,
    const float* __restrict__ rmaxp, float* __restrict__ opart,
    float* __restrict__ lhi, float* __restrict__ llo) {
    extern __shared__ float smf[];
    float* Vs = smf;                           // 128*64
    float* Wt = Vs + 128 * 64;                 // 64*68  (p transposed [j][q])

    int b = blockIdx.y;
    int jc = blockIdx.z;
    int cb = jc * JCHUNK;
    int ce = min(cb + JCHUNK, NPAD);
    int q0 = blockIdx.x * 64;
    int t = threadIdx.x;
    const float* Vb = V + b * CDIM * NPT;
    const float* Sb = S + (size_t)b * NPAD * NPAD;

    int tc = t >> 4, tq2 = t & 15;             // c=8tc+i, q=4tq2+j
    float Ohi[8][4], Olo[8][4];
#pragma unroll
    for (int i = 0; i < 8; i++)
#pragma unroll
        for (int j = 0; j < 4; j++) { Ohi[i][j] = 0.f; Olo[i][j] = 0.f; }

    int pq = t >> 2, pquad = t & 3;
    int myrow = q0 + pq;
    float mx = fmaxf(fmaxf(rmaxp[(b * JSPLIT + 0) * NPAD + myrow],
                           rmaxp[(b * JSPLIT + 1) * NPAD + myrow]),
                     rmaxp[(b * JSPLIT + 2) * NPAD + myrow]);
    float hs = 0.f, ls = 0.f;     // per-thread partial row sum (16 j's per tile)

    for (int j0 = cb; j0 < ce; j0 += 64) {
        __syncthreads();
#pragma unroll
        for (int r = 0; r < 8; r++) {          // V tile [128][64]
            int g = t + 256 * r;
            int c = g >> 4;
            int j4 = (g & 15) << 2;
            float4 vv = make_float4(0.f, 0.f, 0.f, 0.f);
            if (j0 + j4 < NPT) vv = *(const float4*)(Vb + c * NPT + j0 + j4);
            *(float4*)(Vs + c * 64 + j4) = vv;
        }
        {   // P tile: load logits row, exp on the fly, accumulate row sum, transpose
            const float* Pr = Sb + (size_t)myrow * NPAD + j0;
#pragma unroll
            for (int k = 0; k < 4; k++) {
                int jj = pquad * 16 + k * 4;
                float4 s4 = *(const float4*)(Pr + jj);
                float p0 = exp_rn(__fsub_rn(s4.x, mx));
                float p1 = exp_rn(__fsub_rn(s4.y, mx));
                float p2 = exp_rn(__fsub_rn(s4.z, mx));
                float p3 = exp_rn(__fsub_rn(s4.w, mx));
                ts_fold(hs, ls, p0);
                ts_fold(hs, ls, p1);
                ts_fold(hs, ls, p2);
                ts_fold(hs, ls, p3);
                Wt[(jj + 0) * 68 + pq] = p0;
                Wt[(jj + 1) * 68 + pq] = p1;
                Wt[(jj + 2) * 68 + pq] = p2;
                Wt[(jj + 3) * 68 + pq] = p3;
            }
        }
        __syncthreads();
        float O[8][4];
#pragma unroll
        for (int i = 0; i < 8; i++)
#pragma unroll
            for (int j = 0; j < 4; j++) O[i][j] = 0.f;
#pragma unroll
        for (int jt = 0; jt < 64; jt += 4) {
            float4 w0 = *(const float4*)(Wt + (jt + 0) * 68 + 4 * tq2);
            float4 w1 = *(const float4*)(Wt + (jt + 1) * 68 + 4 * tq2);
            float4 w2 = *(const float4*)(Wt + (jt + 2) * 68 + 4 * tq2);
            float4 w3 = *(const float4*)(Wt + (jt + 3) * 68 + 4 * tq2);
            float w0a[4] = {w0.x, w0.y, w0.z, w0.w};
            float w1a[4] = {w1.x, w1.y, w1.z, w1.w};
            float w2a[4] = {w2.x, w2.y, w2.z, w2.w};
            float w3a[4] = {w3.x, w3.y, w3.z, w3.w};
#pragma unroll
            for (int i = 0; i < 8; i++) {
                float4 v = *(const float4*)(Vs + (8 * tc + i) * 64 + jt);
#pragma unroll
                for (int j = 0; j < 4; j++) {
                    O[i][j] += v.x * w0a[j];
                    O[i][j] += v.y * w1a[j];
                    O[i][j] += v.z * w2a[j];
                    O[i][j] += v.w * w3a[j];
                }
            }
        }
#pragma unroll
        for (int i = 0; i < 8; i++)
#pragma unroll
            for (int j = 0; j < 4; j++) ts_fold(Ohi[i][j], Olo[i][j], O[i][j]);
    }
    // reduce the 4 per-thread partial sums of each row (lanes pq*4+pquad, groups of 4)
#pragma unroll
    for (int off = 2; off > 0; off >>= 1) {
        float hh = __shfl_down_sync(0xffffffffu, hs, off, 4);
        float ll = __shfl_down_sync(0xffffffffu, ls, off, 4);
        ts_fold(hs, ls, hh);
        ls = __fadd_rn(ls, ll);
    }
    if (pquad == 0) {
        lhi[(b * JSPLIT + jc) * NPAD + myrow] = hs;
        llo[(b * JSPLIT + jc) * NPAD + myrow] = ls;
    }
    int gq = q0 + 4 * tq2;
    if (gq < NPT) {
        float* ob = opart + (size_t)jc * FEAT_SZ;
#pragma unroll
        for (int i = 0; i < 8; i++) {
            int c = 8 * tc + i;
            float4 r;
            r.x = __fadd_rn(Ohi[i][0], Olo[i][0]);
            r.y = __fadd_rn(Ohi[i][1], Olo[i][1]);
            r.z = __fadd_rn(Ohi[i][2], Olo[i][2]);
            r.w = __fadd_rn(Ohi[i][3], Olo[i][3]);
            *(float4*)(ob + (b * CDIM + c) * NPT + gq) = r;
        }
    }
}

// ---------------- row-sum finalize: rinv = 1/sum (double) -----------------
__global__ void rinv_kernel(const float* __restrict__ lhi, const float* __restrict__ llo,
                            float* __restrict__ rinv) {
    int r = blockIdx.x * 256 + threadIdx.x;
    if (r >= BB * NPAD) return;
    int b = r / NPAD, q = r % NPAD;
    double s = 0.0;
#pragma unroll
    for (int jc = 0; jc < JSPLIT; jc++) {
        int o = (b * JSPLIT + jc) * NPAD + q;
        s += (double)lhi[o] + (double)llo[o];
    }
    rinv[r] = (float)(1.0 / s);
}

// ---------------- combine: msg = (O0+O1+O2) * rinv -----------------
__global__ void combine_kernel(const float* __restrict__ opart, const float* __restrict__ rinv,
                               float* __restrict__ msg) {
    int idx = blockIdx.x * 256 + threadIdx.x;
    if (idx >= FEAT_SZ) return;
    int n = idx % NPT;
    int b = idx / (CDIM * NPT);
    float v = __fadd_rn(__fadd_rn(opart[idx], opart[FEAT_SZ + idx]),
                        opart[2 * (size_t)FEAT_SZ + idx]);
    msg[idx] = __fmul_rn(v, rinv[b * NPAD + n]);
}

// ---------------- final head ----------------
__global__ void conf_kernel(const float* __restrict__ h, const float* __restrict__ w,
                            const float* __restrict__ bias, float* __restrict__ out) {
    int idx = blockIdx.x * 256 + threadIdx.x;
    if (idx >= BB * NPT) return;
    int b = idx / NPT, n = idx % NPT;
    float hi = 0.f, lo = 0.f;
#pragma unroll
    for (int c = 0; c < 32; c++) {
        float a = w[c];
        float v = fmaxf(h[(b * 32 + c) * NPT + n], 0.f);
        float p = __fmul_rn(a, v);
        float e = __fmaf_rn(a, v, -p);
        ts_fold(hi, lo, p);
        lo = __fadd_rn(lo, e);
    }
    out[idx] = __fadd_rn(__fadd_rn(hi, lo), bias[0]);
}

__global__ void norm_kernel(const float* __restrict__ x, float* __restrict__ out) {
    int idx = blockIdx.x * 256 + threadIdx.x;
    if (idx >= BB * NPT) return;
    int b = idx / NPT, n = idx % NPT;
    float hi = 0.f, lo = 0.f;
#pragma unroll 8
    for (int c = 0; c < 128; c++) {
        float v = x[(b * 128 + c) * NPT + n];
        float p = __fmul_rn(v, v);
        float e = __fmaf_rn(v, v, -p);
        ts_fold(hi, lo, p);
        lo = __fadd_rn(lo, e);
    }
    float nf = __fsqrt_rn(__fadd_rn(hi, lo));
    nf = fmaxf(nf, 1e-12f);
#pragma unroll 8
    for (int c = 0; c < 128; c++)
        out[(b * 128 + c) * NPT + n] = __fdiv_rn(x[(b * 128 + c) * NPT + n], nf);
}

// ---------------- host ----------------
extern "C" void kernel_launch(void* const* d_in, const int* in_sizes, int n_in,
                              void* d_out, int out_size) {
    const float* corr   = (const float*)d_in[0];
    const float* src    = (const float*)d_in[1];
    const float* tgt    = (const float*)d_in[2];
    const float* init_W = (const float*)d_in[3];
    const float* init_b = (const float*)d_in[4];
    const float* pcn_W  = (const float*)d_in[5];
    const float* pcn_b  = (const float*)d_in[6];
    const float* pcn_g  = (const float*)d_in[7];
    const float* pcn_be = (const float*)d_in[8];
    const float* qW = (const float*)d_in[9];
    const float* qb = (const float*)d_in[10];
    const float* kW = (const float*)d_in[11];
    const float* kb = (const float*)d_in[12];
    const float* vW = (const float*)d_in[13];
    const float* vb = (const float*)d_in[14];
    const float* m1W = (const float*)d_in[15];
    const float* m1b = (const float*)d_in[16];
    const float* m1g = (const float*)d_in[17];
    const float* m1be = (const float*)d_in[18];
    const float* m2W = (const float*)d_in[19];
    const float* m2b = (const float*)d_in[20];
    const float* m2g = (const float*)d_in[21];
    const float* m2be = (const float*)d_in[22];
    const float* m3W = (const float*)d_in[23];
    const float* m3b = (const float*)d_in[24];
    const float* c1W = (const float*)d_in[25];
    const float* c1b = (const float*)d_in[26];
    const float* c2W = (const float*)d_in[27];
    const float* c2b = (const float*)d_in[28];
    const float* c3W = (const float*)d_in[29];
    const float* c3b = (const float*)d_in[30];
    float* out = (float*)d_out;

    float *x, *tmp, *q, *k, *v, *msg, *h1, *h2, *ss, *ss2, *S;
    float *rmaxp, *lhi, *llo, *rinv, *opart;
    cudaGetSymbolAddress((void**)&x, g_x);
    cudaGetSymbolAddress((void**)&tmp, g_tmp);
    cudaGetSymbolAddress((void**)&q, g_q);
    cudaGetSymbolAddress((void**)&k, g_k);
    cudaGetSymbolAddress((void**)&v, g_v);
    cudaGetSymbolAddress((void**)&msg, g_msg);
    cudaGetSymbolAddress((void**)&h1, g_h1);
    cudaGetSymbolAddress((void**)&h2, g_h2);
    cudaGetSymbolAddress((void**)&ss, g_ss);
    cudaGetSymbolAddress((void**)&ss2, g_ss2);
    cudaGetSymbolAddress((void**)&S, g_S);
    cudaGetSymbolAddress((void**)&rmaxp, g_rmaxp);
    cudaGetSymbolAddress((void**)&lhi, g_lhi);
    cudaGetSymbolAddress((void**)&llo, g_llo);
    cudaGetSymbolAddress((void**)&rinv, g_rinv);
    cudaGetSymbolAddress((void**)&opart, g_opart);

    size_t smem1 = (size_t)(2 * 128 * 64 + 64 * 6) * sizeof(float);
    size_t smem3 = (size_t)(128 * 64 + 64 * 68) * sizeof(float);
    cudaFuncSetAttribute(attn_logits_kernel, cudaFuncAttributeMaxDynamicSharedMemorySize,
                         (int)smem1);
    cudaFuncSetAttribute(attn_pv_kernel, cudaFuncAttributeMaxDynamicSharedMemorySize,
                         (int)smem3);

    const int EW = (FEAT_SZ + 255) / 256;
    dim3 cg128(47, 2, BB);   // Cout=128
    dim3 cg64(47, 1, BB);    // Cout<=64
    dim3 ag(47, BB, JSPLIT);

    init_embed_kernel<<<EW, 256>>>(corr, init_W, init_b, x);

    for (int i = 0; i < NLAYERS; i++) {
        // PointCN conv + stats; BN/relu folded into consumers
        conv_kernel<<<cg128, 256>>>(x, pcn_W + i * 128 * 128, pcn_b + i * 128, tmp,
                                    nullptr, 0, 128, 128);
        bn_stats_kernel<<<128, 256>>>(tmp, pcn_g + i * 128, pcn_be + i * 128, ss, 128);
        // Q,K,V directly from tmp with BN+relu input transform
        conv_kernel<<<cg128, 256>>>(tmp, qW + i * 16384, qb + i * 128, q, ss, 1, 128, 128);
        conv_kernel<<<cg128, 256>>>(tmp, kW + i * 16384, kb + i * 128, k, ss, 1, 128, 128);
        conv_kernel<<<cg128, 256>>>(tmp, vW + i * 16384, vb + i * 128, v, ss, 1, 128, 128);
        // attention: logits (j-split), fused exp+PV (j-split), finalize
        attn_logits_kernel<<<ag, 256, smem1>>>(q, k, src, tgt, S, rmaxp);
        attn_pv_kernel<<<ag, 256, smem3>>>(v, S, rmaxp, opart, lhi, llo);
        rinv_kernel<<<(BB * NPAD + 255) / 256, 256>>>(lhi, llo, rinv);
        combine_kernel<<<EW, 256>>>(opart, rinv, msg);
        // msg MLP
        conv_kernel<<<cg64, 256>>>(msg, m1W + i * 64 * 128, m1b + i * 64, h1,
                                   nullptr, 0, 64, 128);
        bn_stats_kernel<<<64, 256>>>(h1, m1g + i * 64, m1be + i * 64, ss2, 64);
        conv_kernel<<<cg64, 256>>>(h1, m2W + i * 64 * 64, m2b + i * 64, h2, ss2, 1, 64, 64);
        bn_stats_kernel<<<64, 256>>>(h2, m2g + i * 64, m2be + i * 64, ss2, 64);
        conv_kernel<<<cg128, 256>>>(h2, m3W + i * 128 * 64, m3b + i * 128, msg, ss2, 1, 128, 64);
        // residual with BN fold: x = relu(bn(tmp)) + msg
        bn_add_kernel<<<EW, 256>>>(tmp, ss, msg, x);
    }

    conv_kernel<<<cg64, 256>>>(x, c1W, c1b, h1, nullptr, 0, 32, 128);
    conv_kernel<<<cg64, 256>>>(h1, c2W, c2b, h2, nullptr, 1, 32, 32);
    conf_kernel<<<(BB * NPT + 255) / 256, 256>>>(h2, c3W, c3b, out);
    norm_kernel<<<(BB * NPT + 255) / 256, 256>>>(x, out + BB * NPT);
}

// round 13
// speedup vs baseline: 1.5500x; 1.0893x over previous
#include <cuda_runtime.h>
#include <math.h>

#define NPT 3000
#define NPAD 3008
#define CDIM 128
#define BB 2
#define NLAYERS 6
#define FEAT_SZ (BB*CDIM*NPT)
#define JSPLIT 3
#define JCHUNK 1024

// ---------------- scratch ----------------
__device__ float g_x[FEAT_SZ];
__device__ float g_tmp[FEAT_SZ];
__device__ float g_q[FEAT_SZ];
__device__ float g_k[FEAT_SZ];
__device__ float g_v[FEAT_SZ];
__device__ float g_msg[FEAT_SZ];
__device__ float g_h1[BB*64*NPT];
__device__ float g_h2[BB*64*NPT];
__device__ float g_ss[4*CDIM];
__device__ float g_ss2[4*CDIM];
__device__ float g_S[(size_t)BB * NPAD * NPAD];
__device__ float g_rmaxp[JSPLIT*BB*NPAD];
__device__ float g_lhi[JSPLIT*BB*NPAD];
__device__ float g_llo[JSPLIT*BB*NPAD];
__device__ float g_rinv[BB*NPAD];
__device__ float g_opart[(size_t)JSPLIT*FEAT_SZ];

__device__ __forceinline__ void ts_fold(float& hi, float& lo, float p) {
    float t = __fadd_rn(hi, p);
    float z = __fsub_rn(t, hi);
    float e = __fadd_rn(__fsub_rn(hi, __fsub_rn(t, z)), __fsub_rn(p, z));
    lo = __fadd_rn(lo, e);
    hi = t;
}

__device__ __forceinline__ float exp_rn(float x) {
    if (x < -87.336544f) return 0.0f;
    float kf = rintf(__fmul_rn(x, 1.4426950408889634f));
    float r = __fmaf_rn(-kf, 0.693359375f, x);
    r = __fmaf_rn(-kf, -2.12194440e-4f, r);
    float z = 1.9875691500e-4f;
    z = __fmaf_rn(z, r, 1.3981999507e-3f);
    z = __fmaf_rn(z, r, 8.3334519073e-3f);
    z = __fmaf_rn(z, r, 4.1665795894e-2f);
    z = __fmaf_rn(z, r, 1.6666665459e-1f);
    z = __fmaf_rn(z, r, 5.0000001201e-1f);
    float rr = __fmul_rn(r, r);
    float e = __fadd_rn(__fmaf_rn(z, rr, r), 1.0f);
    int k = (int)kf;
    float s = __int_as_float((k + 127) << 23);
    return __fmul_rn(e, s);
}

__device__ __forceinline__ float bn_xform(float x, float m, float g, float ri, float be) {
    float t = __fsub_rn(x, m);
    t = __fmul_rn(g, t);
    return __fmaf_rn(t, ri, be);
}

// ---------------- init embedding ----------------
__global__ void init_embed_kernel(const float* __restrict__ corr,
                                  const float* __restrict__ W,
                                  const float* __restrict__ bias,
                                  float* __restrict__ out) {
    int idx = blockIdx.x * blockDim.x + threadIdx.x;
    if (idx >= FEAT_SZ) return;
    int n = idx % NPT;
    int c = (idx / NPT) % CDIM;
    int b = idx / (CDIM * NPT);
    const float* cp = corr + (b * NPT + n) * 6;
    float hi = 0.f, lo = 0.f;
#pragma unroll
    for (int k = 0; k < 6; k++) {
        float a = W[c * 6 + k], bb = cp[k];
        float p = __fmul_rn(a, bb);
        float e = __fmaf_rn(a, bb, -p);
        ts_fold(hi, lo, p);
        lo = __fadd_rn(lo, e);
    }
    out[idx] = __fadd_rn(__fadd_rn(hi, lo), bias[c]);
}

// ---------------- generic pointwise conv ----------------
__global__ __launch_bounds__(256) void conv_kernel(
    const float* __restrict__ in, const float* __restrict__ W,
    const float* __restrict__ bias, float* __restrict__ out,
    const float* __restrict__ ss, int relu, int Cout, int Cin) {
    __shared__ float Ws[16 * 68];
    __shared__ float Is[16 * 68];
    int b = blockIdx.z;
    int o0 = blockIdx.y * 64;
    int p0 = blockIdx.x * 64;
    int t = threadIdx.x;
    int to = t >> 4, tp = t & 15;
    float hi[4][4], lo[4][4];
#pragma unroll
    for (int i = 0; i < 4; i++)
#pragma unroll
        for (int j = 0; j < 4; j++) { hi[i][j] = 0.f; lo[i][j] = 0.f; }

    for (int c0 = 0; c0 < Cin; c0 += 16) {
        __syncthreads();
        {
            int oo = t >> 2, cg = (t & 3) << 2;
            int o = o0 + oo;
            float4 w = make_float4(0.f, 0.f, 0.f, 0.f);
            if (o < Cout) w = *(const float4*)(W + o * Cin + c0 + cg);
            Ws[(cg + 0) * 68 + oo] = w.x;
            Ws[(cg + 1) * 68 + oo] = w.y;
            Ws[(cg + 2) * 68 + oo] = w.z;
            Ws[(cg + 3) * 68 + oo] = w.w;
        }
        {
            int cc = t >> 4, pg = (t & 15) << 2;
            int c = c0 + cc;
            int p = p0 + pg;
            float4 v = make_float4(0.f, 0.f, 0.f, 0.f);
            if (p < NPT) v = *(const float4*)(in + (b * Cin + c) * NPT + p);
            if (ss) {
                float m = ss[4 * c], g = ss[4 * c + 1], ri = ss[4 * c + 2], be = ss[4 * c + 3];
                v.x = bn_xform(v.x, m, g, ri, be);
                v.y = bn_xform(v.y, m, g, ri, be);
                v.z = bn_xform(v.z, m, g, ri, be);
                v.w = bn_xform(v.w, m, g, ri, be);
            }
            if (relu) {
                v.x = fmaxf(v.x, 0.f); v.y = fmaxf(v.y, 0.f);
                v.z = fmaxf(v.z, 0.f); v.w = fmaxf(v.w, 0.f);
            }
            *(float4*)(Is + cc * 68 + pg) = v;
        }
        __syncthreads();
        float acc[4][4];
#pragma unroll
        for (int i = 0; i < 4; i++)
#pragma unroll
            for (int j = 0; j < 4; j++) acc[i][j] = 0.f;
#pragma unroll
        for (int cc = 0; cc < 16; cc++) {
            float4 a = *(const float4*)(Ws + cc * 68 + 4 * to);
            float4 bb = *(const float4*)(Is + cc * 68 + 4 * tp);
            float av[4] = {a.x, a.y, a.z, a.w};
            float bv[4] = {bb.x, bb.y, bb.z, bb.w};
#pragma unroll
            for (int i = 0; i < 4; i++)
#pragma unroll
                for (int j = 0; j < 4; j++) acc[i][j] += av[i] * bv[j];
        }
#pragma unroll
        for (int i = 0; i < 4; i++)
#pragma unroll
            for (int j = 0; j < 4; j++) ts_fold(hi[i][j], lo[i][j], acc[i][j]);
    }
    int p = p0 + 4 * tp;
    if (p < NPT) {
#pragma unroll
        for (int i = 0; i < 4; i++) {
            int o = o0 + 4 * to + i;
            if (o < Cout) {
                float bi = bias[o];
                float4 r;
                r.x = __fadd_rn(__fadd_rn(hi[i][0], lo[i][0]), bi);
                r.y = __fadd_rn(__fadd_rn(hi[i][1], lo[i][1]), bi);
                r.z = __fadd_rn(__fadd_rn(hi[i][2], lo[i][2]), bi);
                r.w = __fadd_rn(__fadd_rn(hi[i][3], lo[i][3]), bi);
                *(float4*)(out + (b * Cout + o) * NPT + p) = r;
            }
        }
    }
}

// ---------------- fused Q/K/V conv: blockIdx.y = sel*2 + (o0/64) ----------------
__global__ __launch_bounds__(256) void conv3_kernel(
    const float* __restrict__ in,
    const float* __restrict__ Wq, const float* __restrict__ Wk, const float* __restrict__ Wv,
    const float* __restrict__ bq, const float* __restrict__ bk, const float* __restrict__ bv,
    float* __restrict__ oq, float* __restrict__ ok, float* __restrict__ ov,
    const float* __restrict__ ss) {
    __shared__ float Ws[16 * 68];
    __shared__ float Is[16 * 68];
    int b = blockIdx.z;
    int sel = blockIdx.y >> 1;
    int o0 = (blockIdx.y & 1) * 64;
    const float* W = sel == 0 ? Wq : (sel == 1 ? Wk : Wv);
    const float* bias = sel == 0 ? bq : (sel == 1 ? bk : bv);
    float* out = sel == 0 ? oq : (sel == 1 ? ok : ov);
    int p0 = blockIdx.x * 64;
    int t = threadIdx.x;
    int to = t >> 4, tp = t & 15;
    float hi[4][4], lo[4][4];
#pragma unroll
    for (int i = 0; i < 4; i++)
#pragma unroll
        for (int j = 0; j < 4; j++) { hi[i][j] = 0.f; lo[i][j] = 0.f; }

    for (int c0 = 0; c0 < 128; c0 += 16) {
        __syncthreads();
        {
            int oo = t >> 2, cg = (t & 3) << 2;
            float4 w = *(const float4*)(W + (o0 + oo) * 128 + c0 + cg);
            Ws[(cg + 0) * 68 + oo] = w.x;
            Ws[(cg + 1) * 68 + oo] = w.y;
            Ws[(cg + 2) * 68 + oo] = w.z;
            Ws[(cg + 3) * 68 + oo] = w.w;
        }
        {
            int cc = t >> 4, pg = (t & 15) << 2;
            int c = c0 + cc;
            int p = p0 + pg;
            float4 v = make_float4(0.f, 0.f, 0.f, 0.f);
            if (p < NPT) v = *(const float4*)(in + (b * 128 + c) * NPT + p);
            float m = ss[4 * c], g = ss[4 * c + 1], ri = ss[4 * c + 2], be = ss[4 * c + 3];
            v.x = fmaxf(bn_xform(v.x, m, g, ri, be), 0.f);
            v.y = fmaxf(bn_xform(v.y, m, g, ri, be), 0.f);
            v.z = fmaxf(bn_xform(v.z, m, g, ri, be), 0.f);
            v.w = fmaxf(bn_xform(v.w, m, g, ri, be), 0.f);
            *(float4*)(Is + cc * 68 + pg) = v;
        }
        __syncthreads();
        float acc[4][4];
#pragma unroll
        for (int i = 0; i < 4; i++)
#pragma unroll
            for (int j = 0; j < 4; j++) acc[i][j] = 0.f;
#pragma unroll
        for (int cc = 0; cc < 16; cc++) {
            float4 a = *(const float4*)(Ws + cc * 68 + 4 * to);
            float4 bb = *(const float4*)(Is + cc * 68 + 4 * tp);
            float av[4] = {a.x, a.y, a.z, a.w};
            float bv[4] = {bb.x, bb.y, bb.z, bb.w};
#pragma unroll
            for (int i = 0; i < 4; i++)
#pragma unroll
                for (int j = 0; j < 4; j++) acc[i][j] += av[i] * bv[j];
        }
#pragma unroll
        for (int i = 0; i < 4; i++)
#pragma unroll
            for (int j = 0; j < 4; j++) ts_fold(hi[i][j], lo[i][j], acc[i][j]);
    }
    int p = p0 + 4 * tp;
    if (p < NPT) {
#pragma unroll
        for (int i = 0; i < 4; i++) {
            int o = o0 + 4 * to + i;
            float bi = bias[o];
            float4 r;
            r.x = __fadd_rn(__fadd_rn(hi[i][0], lo[i][0]), bi);
            r.y = __fadd_rn(__fadd_rn(hi[i][1], lo[i][1]), bi);
            r.z = __fadd_rn(__fadd_rn(hi[i][2], lo[i][2]), bi);
            r.w = __fadd_rn(__fadd_rn(hi[i][3], lo[i][3]), bi);
            *(float4*)(out + (b * 128 + o) * NPT + p) = r;
        }
    }
}

// ---------------- m1 conv with attention-combine folded into input ----------------
__global__ __launch_bounds__(256) void conv_m1_kernel(
    const float* __restrict__ opart, const float* __restrict__ rinv,
    const float* __restrict__ W, const float* __restrict__ bias,
    float* __restrict__ out) {
    __shared__ float Ws[16 * 68];
    __shared__ float Is[16 * 68];
    int b = blockIdx.z;
    int p0 = blockIdx.x * 64;
    int t = threadIdx.x;
    int to = t >> 4, tp = t & 15;
    float hi[4][4], lo[4][4];
#pragma unroll
    for (int i = 0; i < 4; i++)
#pragma unroll
        for (int j = 0; j < 4; j++) { hi[i][j] = 0.f; lo[i][j] = 0.f; }

    for (int c0 = 0; c0 < 128; c0 += 16) {
        __syncthreads();
        {
            int oo = t >> 2, cg = (t & 3) << 2;
            float4 w = *(const float4*)(W + oo * 128 + c0 + cg);
            Ws[(cg + 0) * 68 + oo] = w.x;
            Ws[(cg + 1) * 68 + oo] = w.y;
            Ws[(cg + 2) * 68 + oo] = w.z;
            Ws[(cg + 3) * 68 + oo] = w.w;
        }
        {
            int cc = t >> 4, pg = (t & 15) << 2;
            int c = c0 + cc;
            int p = p0 + pg;
            float4 v = make_float4(0.f, 0.f, 0.f, 0.f);
            if (p < NPT) {
                size_t off = (size_t)(b * 128 + c) * NPT + p;
                float4 a0 = *(const float4*)(opart + off);
                float4 a1 = *(const float4*)(opart + FEAT_SZ + off);
                float4 a2 = *(const float4*)(opart + 2 * (size_t)FEAT_SZ + off);
                float4 rv = *(const float4*)(rinv + b * NPAD + p);
                v.x = __fmul_rn(__fadd_rn(__fadd_rn(a0.x, a1.x), a2.x), rv.x);
                v.y = __fmul_rn(__fadd_rn(__fadd_rn(a0.y, a1.y), a2.y), rv.y);
                v.z = __fmul_rn(__fadd_rn(__fadd_rn(a0.z, a1.z), a2.z), rv.z);
                v.w = __fmul_rn(__fadd_rn(__fadd_rn(a0.w, a1.w), a2.w), rv.w);
            }
            *(float4*)(Is + cc * 68 + pg) = v;
        }
        __syncthreads();
        float acc[4][4];
#pragma unroll
        for (int i = 0; i < 4; i++)
#pragma unroll
            for (int j = 0; j < 4; j++) acc[i][j] = 0.f;
#pragma unroll
        for (int cc = 0; cc < 16; cc++) {
            float4 a = *(const float4*)(Ws + cc * 68 + 4 * to);
            float4 bb = *(const float4*)(Is + cc * 68 + 4 * tp);
            float av[4] = {a.x, a.y, a.z, a.w};
            float bv[4] = {bb.x, bb.y, bb.z, bb.w};
#pragma unroll
            for (int i = 0; i < 4; i++)
#pragma unroll
                for (int j = 0; j < 4; j++) acc[i][j] += av[i] * bv[j];
        }
#pragma unroll
        for (int i = 0; i < 4; i++)
#pragma unroll
            for (int j = 0; j < 4; j++) ts_fold(hi[i][j], lo[i][j], acc[i][j]);
    }
    int p = p0 + 4 * tp;
    if (p < NPT) {
#pragma unroll
        for (int i = 0; i < 4; i++) {
            int o = 4 * to + i;
            float bi = bias[o];
            float4 r;
            r.x = __fadd_rn(__fadd_rn(hi[i][0], lo[i][0]), bi);
            r.y = __fadd_rn(__fadd_rn(hi[i][1], lo[i][1]), bi);
            r.z = __fadd_rn(__fadd_rn(hi[i][2], lo[i][2]), bi);
            r.w = __fadd_rn(__fadd_rn(hi[i][3], lo[i][3]), bi);
            *(float4*)(out + (b * 64 + o) * NPT + p) = r;
        }
    }
}

// ---------------- BN batch stats ----------------
__global__ void bn_stats_kernel(const float* __restrict__ x, const float* __restrict__ g,
                                const float* __restrict__ beta, float* __restrict__ ss, int Cc) {
    __shared__ float shi[256], slo[256], qhi[256], qlo[256];
    int o = blockIdx.x;
    int t = threadIdx.x;
    const float* p0 = x + o * NPT;
    const float* p1 = x + (Cc + o) * NPT;
    float hs = 0.f, ls = 0.f, hq = 0.f, lq = 0.f;
    for (int i = t; i < NPT; i += 256) {
        float v = p0[i];
        ts_fold(hs, ls, v);
        float p = __fmul_rn(v, v);
        float e = __fmaf_rn(v, v, -p);
        ts_fold(hq, lq, p);
        lq = __fadd_rn(lq, e);
        float w = p1[i];
        ts_fold(hs, ls, w);
        p = __fmul_rn(w, w);
        e = __fmaf_rn(w, w, -p);
        ts_fold(hq, lq, p);
        lq = __fadd_rn(lq, e);
    }
    shi[t] = hs; slo[t] = ls; qhi[t] = hq; qlo[t] = lq;
    __syncthreads();
    for (int off = 128; off > 0; off >>= 1) {
        if (t < off) {
            float h2 = shi[t], l2 = slo[t];
            ts_fold(h2, l2, shi[t + off]);
            l2 = __fadd_rn(l2, slo[t + off]);
            shi[t] = h2; slo[t] = l2;
            h2 = qhi[t]; l2 = qlo[t];
            ts_fold(h2, l2, qhi[t + off]);
            l2 = __fadd_rn(l2, qlo[t + off]);
            qhi[t] = h2; qlo[t] = l2;
        }
        __syncthreads();
    }
    if (t == 0) {
        double mean = ((double)shi[0] + (double)slo[0]) * (1.0 / 6000.0);
        double msq = ((double)qhi[0] + (double)qlo[0]) * (1.0 / 6000.0);
        double var = msq - mean * mean;
        ss[4 * o + 0] = (float)mean;
        ss[4 * o + 1] = g[o];
        ss[4 * o + 2] = (float)(1.0 / sqrt(var + 1e-5));
        ss[4 * o + 3] = beta[o];
    }
}

__global__ void bn_add_kernel(const float* __restrict__ tmp, const float* __restrict__ ss,
                              const float* __restrict__ msg, float* __restrict__ x) {
    int idx = blockIdx.x * 256 + threadIdx.x;
    if (idx >= FEAT_SZ) return;
    int c = (idx / NPT) % CDIM;
    float v = bn_xform(tmp[idx], ss[4 * c], ss[4 * c + 1], ss[4 * c + 2], ss[4 * c + 3]);
    x[idx] = __fadd_rn(fmaxf(v, 0.f), msg[idx]);
}

// ---------------- attention pass 1: 128q x 64j tiles, single wave (144 CTAs) ----------
__global__ __launch_bounds__(256, 1) void attn_logits_kernel(
    const float* __restrict__ Q, const float* __restrict__ K,
    const float* __restrict__ src, const float* __restrict__ tgt,
    float* __restrict__ S, float* __restrict__ rmaxp) {
    extern __shared__ float sm[];
    float* Qs = sm;                    // 128c x 128q
    float* Ks = Qs + 128 * 128;        // 128c x 64j
    float* qc = Ks + 128 * 64;         // 128*6
    float* kc = qc + 128 * 6;          // 64*6

    int b = blockIdx.y;
    int jc = blockIdx.z;
    int cb = jc * JCHUNK;
    int ce = min(cb + JCHUNK, NPAD);
    int q0 = blockIdx.x * 128;
    int t = threadIdx.x;
    const float SCALE = __fdiv_rn(1.0f, __fsqrt_rn(128.0f));

    const float* Qb = Q + b * CDIM * NPT;
    const float* Kb = K + b * CDIM * NPT;
    float* Sb = S + (size_t)b * NPAD * NPAD;

#pragma unroll
    for (int r = 0; r < 16; r++) {   // Q tile [128c][128q]
        int g = t + 256 * r;
        int c = g >> 5;
        int q4 = (g & 31) << 2;
        float4 v = make_float4(0.f, 0.f, 0.f, 0.f);
        if (q0 + q4 < NPT) v = *(const float4*)(Qb + c * NPT + q0 + q4);
        *(float4*)(Qs + c * 128 + q4) = v;
    }
    if (t < 128) {
        int gq = q0 + t;
#pragma unroll
        for (int k = 0; k < 3; k++) {
            qc[t * 6 + k]     = (gq < NPT) ? src[(b * NPT + gq) * 3 + k] : 0.f;
            qc[t * 6 + 3 + k] = (gq < NPT) ? tgt[(b * NPT + gq) * 3 + k] : 0.f;
        }
    }

    int tq = t >> 4, tk = t & 15;     // q = tq*8 + i (i<8), j = tk*4 + j
    float rm[8];
#pragma unroll
    for (int i = 0; i < 8; i++) rm[i] = -1e30f;

    for (int j0 = cb; j0 < ce; j0 += 64) {
        __syncthreads();
#pragma unroll
        for (int r = 0; r < 8; r++) {   // K tile [128c][64j]
            int g = t + 256 * r;
            int c = g >> 4;
            int j4 = (g & 15) << 2;
            float4 kv = make_float4(0.f, 0.f, 0.f, 0.f);
            if (j0 + j4 < NPT) kv = *(const float4*)(Kb + c * NPT + j0 + j4);
            *(float4*)(Ks + c * 64 + j4) = kv;
        }
        if (t < 64) {
            int gj = j0 + t;
#pragma unroll
            for (int k = 0; k < 3; k++) {
                kc[t * 6 + k]     = (gj < NPT) ? src[(b * NPT + gj) * 3 + k] : 0.f;
                kc[t * 6 + 3 + k] = (gj < NPT) ? tgt[(b * NPT + gj) * 3 + k] : 0.f;
            }
        }
        __syncthreads();

        float dhi[8][4], dlo[8][4];
#pragma unroll
        for (int i = 0; i < 8; i++)
#pragma unroll
            for (int j = 0; j < 4; j++) { dhi[i][j] = 0.f; dlo[i][j] = 0.f; }
#pragma unroll 1
        for (int ch = 0; ch < 8; ch++) {
            float s[8][4];
#pragma unroll
            for (int i = 0; i < 8; i++)
#pragma unroll
                for (int j = 0; j < 4; j++) s[i][j] = 0.f;
#pragma unroll
            for (int cc = 0; cc < 16; cc++) {
                int c = ch * 16 + cc;
                float4 a0 = *(const float4*)(Qs + c * 128 + 8 * tq);
                float4 a1 = *(const float4*)(Qs + c * 128 + 8 * tq + 4);
                float4 bb = *(const float4*)(Ks + c * 64 + 4 * tk);
                float av[8] = {a0.x, a0.y, a0.z, a0.w, a1.x, a1.y, a1.z, a1.w};
                float bv[4] = {bb.x, bb.y, bb.z, bb.w};
#pragma unroll
                for (int i = 0; i < 8; i++)
#pragma unroll
                    for (int j = 0; j < 4; j++) s[i][j] += av[i] * bv[j];
            }
#pragma unroll
            for (int i = 0; i < 8; i++)
#pragma unroll
                for (int j = 0; j < 4; j++) ts_fold(dhi[i][j], dlo[i][j], s[i][j]);
        }
#pragma unroll
        for (int i = 0; i < 8; i++) {
            int row = q0 + tq * 8 + i;
            float qs0 = qc[(tq * 8 + i) * 6 + 0], qs1 = qc[(tq * 8 + i) * 6 + 1];
            float qs2 = qc[(tq * 8 + i) * 6 + 2];
            float qt0 = qc[(tq * 8 + i) * 6 + 3], qt1 = qc[(tq * 8 + i) * 6 + 4];
            float qt2 = qc[(tq * 8 + i) * 6 + 5];
            float lg[4];
#pragma unroll
            for (int j = 0; j < 4; j++) {
                int jj = 4 * tk + j;
                int gj = j0 + jj;
                float dx = __fsub_rn(qs0, kc[jj * 6 + 0]);
                float dy = __fsub_rn(qs1, kc[jj * 6 + 1]);
                float dz = __fsub_rn(qs2, kc[jj * 6 + 2]);
                float d2s = __fmaf_rn(dz, dz, __fmaf_rn(dy, dy, __fmul_rn(dx, dx)));
                float ds = __fsqrt_rn(d2s);
                dx = __fsub_rn(qt0, kc[jj * 6 + 3]);
                dy = __fsub_rn(qt1, kc[jj * 6 + 4]);
                dz = __fsub_rn(qt2, kc[jj * 6 + 5]);
                float d2t = __fmaf_rn(dz, dz, __fmaf_rn(dy, dy, __fmul_rn(dx, dx)));
                float dt = __fsqrt_rn(d2t);
                float dd = __fsub_rn(ds, dt);
                float sc = fmaxf(__fmaf_rn(-dd, dd, 1.0f), 0.f);
                float dot = __fadd_rn(dhi[i][j], dlo[i][j]);
                float logit = __fmul_rn(sc, __fmul_rn(dot, SCALE));
                if (gj >= NPT) logit = -1e30f;
                lg[j] = logit;
                rm[i] = fmaxf(rm[i], logit);
            }
            if (row < NPAD)
                *(float4*)(Sb + (size_t)row * NPAD + j0 + 4 * tk) =
                    make_float4(lg[0], lg[1], lg[2], lg[3]);
        }
    }
#pragma unroll
    for (int i = 0; i < 8; i++) {
#pragma unroll
        for (int off = 8; off > 0; off >>= 1)
            rm[i] = fmaxf(rm[i], __shfl_xor_sync(0xffffffffu, rm[i], off, 16));
        int row = q0 + tq * 8 + i;
        if (tk == 0 && row < NPAD) rmaxp[(b * JSPLIT + jc) * NPAD + row] = rm[i];
    }
}

// ---------------- attention pass 2: fused exp + partial PV + row sums ----------------
__global__ __launch_bounds__(256, 1) void attn_pv_kernel(
    const float* __restrict__ V, const float* __restrict__ S,
    const float* __restrict__ rmaxp, float* __restrict__ opart,
    float* __restrict__ lhi, float* __restrict__ llo) {
    extern __shared__ float smf[];
    float* Vs = smf;                           // 128*64
    float* Wt = Vs + 128 * 64;                 // 64*68

    int b = blockIdx.y;
    int jc = blockIdx.z;
    int cb = jc * JCHUNK;
    int ce = min(cb + JCHUNK, NPAD);
    int q0 = blockIdx.x * 64;
    int t = threadIdx.x;
    const float* Vb = V + b * CDIM * NPT;
    const float* Sb = S + (size_t)b * NPAD * NPAD;

    int tc = t >> 4, tq2 = t & 15;
    float Ohi[8][4], Olo[8][4];
#pragma unroll
    for (int i = 0; i < 8; i++)
#pragma unroll
        for (int j = 0; j < 4; j++) { Ohi[i][j] = 0.f; Olo[i][j] = 0.f; }

    int pq = t >> 2, pquad = t & 3;
    int myrow = q0 + pq;
    float mx = fmaxf(fmaxf(rmaxp[(b * JSPLIT + 0) * NPAD + myrow],
                           rmaxp[(b * JSPLIT + 1) * NPAD + myrow]),
                     rmaxp[(b * JSPLIT + 2) * NPAD + myrow]);
    float hs = 0.f, ls = 0.f;

    for (int j0 = cb; j0 < ce; j0 += 64) {
        __syncthreads();
#pragma unroll
        for (int r = 0; r < 8; r++) {
            int g = t + 256 * r;
            int c = g >> 4;
            int j4 = (g & 15) << 2;
            float4 vv = make_float4(0.f, 0.f, 0.f, 0.f);
            if (j0 + j4 < NPT) vv = *(const float4*)(Vb + c * NPT + j0 + j4);
            *(float4*)(Vs + c * 64 + j4) = vv;
        }
        {
            const float* Pr = Sb + (size_t)myrow * NPAD + j0;
#pragma unroll
            for (int k = 0; k < 4; k++) {
                int jj = pquad * 16 + k * 4;
                float4 s4 = *(const float4*)(Pr + jj);
                float p0 = exp_rn(__fsub_rn(s4.x, mx));
                float p1 = exp_rn(__fsub_rn(s4.y, mx));
                float p2 = exp_rn(__fsub_rn(s4.z, mx));
                float p3 = exp_rn(__fsub_rn(s4.w, mx));
                ts_fold(hs, ls, p0);
                ts_fold(hs, ls, p1);
                ts_fold(hs, ls, p2);
                ts_fold(hs, ls, p3);
                Wt[(jj + 0) * 68 + pq] = p0;
                Wt[(jj + 1) * 68 + pq] = p1;
                Wt[(jj + 2) * 68 + pq] = p2;
                Wt[(jj + 3) * 68 + pq] = p3;
            }
        }
        __syncthreads();
        float O[8][4];
#pragma unroll
        for (int i = 0; i < 8; i++)
#pragma unroll
            for (int j = 0; j < 4; j++) O[i][j] = 0.f;
#pragma unroll
        for (int jt = 0; jt < 64; jt += 4) {
            float4 w0 = *(const float4*)(Wt + (jt + 0) * 68 + 4 * tq2);
            float4 w1 = *(const float4*)(Wt + (jt + 1) * 68 + 4 * tq2);
            float4 w2 = *(const float4*)(Wt + (jt + 2) * 68 + 4 * tq2);
            float4 w3 = *(const float4*)(Wt + (jt + 3) * 68 + 4 * tq2);
            float w0a[4] = {w0.x, w0.y, w0.z, w0.w};
            float w1a[4] = {w1.x, w1.y, w1.z, w1.w};
            float w2a[4] = {w2.x, w2.y, w2.z, w2.w};
            float w3a[4] = {w3.x, w3.y, w3.z, w3.w};
#pragma unroll
            for (int i = 0; i < 8; i++) {
                float4 v = *(const float4*)(Vs + (8 * tc + i) * 64 + jt);
#pragma unroll
                for (int j = 0; j < 4; j++) {
                    O[i][j] += v.x * w0a[j];
                    O[i][j] += v.y * w1a[j];
                    O[i][j] += v.z * w2a[j];
                    O[i][j] += v.w * w3a[j];
                }
            }
        }
#pragma unroll
        for (int i = 0; i < 8; i++)
#pragma unroll
            for (int j = 0; j < 4; j++) ts_fold(Ohi[i][j], Olo[i][j], O[i][j]);
    }
#pragma unroll
    for (int off = 2; off > 0; off >>= 1) {
        float hh = __shfl_down_sync(0xffffffffu, hs, off, 4);
        float ll = __shfl_down_sync(0xffffffffu, ls, off, 4);
        ts_fold(hs, ls, hh);
        ls = __fadd_rn(ls, ll);
    }
    if (pquad == 0) {
        lhi[(b * JSPLIT + jc) * NPAD + myrow] = hs;
        llo[(b * JSPLIT + jc) * NPAD + myrow] = ls;
    }
    int gq = q0 + 4 * tq2;
    if (gq < NPT) {
        float* ob = opart + (size_t)jc * FEAT_SZ;
#pragma unroll
        for (int i = 0; i < 8; i++) {
            int c = 8 * tc + i;
            float4 r;
            r.x = __fadd_rn(Ohi[i][0], Olo[i][0]);
            r.y = __fadd_rn(Ohi[i][1], Olo[i][1]);
            r.z = __fadd_rn(Ohi[i][2], Olo[i][2]);
            r.w = __fadd_rn(Ohi[i][3], Olo[i][3]);
            *(float4*)(ob + (b * CDIM + c) * NPT + gq) = r;
        }
    }
}

__global__ void rinv_kernel(const float* __restrict__ lhi, const float* __restrict__ llo,
                            float* __restrict__ rinv) {
    int r = blockIdx.x * 256 + threadIdx.x;
    if (r >= BB * NPAD) return;
    int b = r / NPAD, q = r % NPAD;
    double s = 0.0;
#pragma unroll
    for (int jc = 0; jc < JSPLIT; jc++) {
        int o = (b * JSPLIT + jc) * NPAD + q;
        s += (double)lhi[o] + (double)llo[o];
    }
    rinv[r] = (float)(1.0 / s);
}

// ---------------- final head ----------------
__global__ void conf_kernel(const float* __restrict__ h, const float* __restrict__ w,
                            const float* __restrict__ bias, float* __restrict__ out) {
    int idx = blockIdx.x * 256 + threadIdx.x;
    if (idx >= BB * NPT) return;
    int b = idx / NPT, n = idx % NPT;
    float hi = 0.f, lo = 0.f;
#pragma unroll
    for (int c = 0; c < 32; c++) {
        float a = w[c];
        float v = fmaxf(h[(b * 32 + c) * NPT + n], 0.f);
        float p = __fmul_rn(a, v);
        float e = __fmaf_rn(a, v, -p);
        ts_fold(hi, lo, p);
        lo = __fadd_rn(lo, e);
    }
    out[idx] = __fadd_rn(__fadd_rn(hi, lo), bias[0]);
}

__global__ void norm_kernel(const float* __restrict__ x, float* __restrict__ out) {
    int idx = blockIdx.x * 256 + threadIdx.x;
    if (idx >= BB * NPT) return;
    int b = idx / NPT, n = idx % NPT;
    float hi = 0.f, lo = 0.f;
#pragma unroll 8
    for (int c = 0; c < 128; c++) {
        float v = x[(b * 128 + c) * NPT + n];
        float p = __fmul_rn(v, v);
        float e = __fmaf_rn(v, v, -p);
        ts_fold(hi, lo, p);
        lo = __fadd_rn(lo, e);
    }
    float nf = __fsqrt_rn(__fadd_rn(hi, lo));
    nf = fmaxf(nf, 1e-12f);
#pragma unroll 8
    for (int c = 0; c < 128; c++)
        out[(b * 128 + c) * NPT + n] = __fdiv_rn(x[(b * 128 + c) * NPT + n], nf);
}

// ---------------- host ----------------
extern "C" void kernel_launch(void* const* d_in, const int* in_sizes, int n_in,
                              void* d_out, int out_size) {
    const float* corr   = (const float*)d_in[0];
    const float* src    = (const float*)d_in[1];
    const float* tgt    = (const float*)d_in[2];
    const float* init_W = (const float*)d_in[3];
    const float* init_b = (const float*)d_in[4];
    const float* pcn_W  = (const float*)d_in[5];
    const float* pcn_b  = (const float*)d_in[6];
    const float* pcn_g  = (const float*)d_in[7];
    const float* pcn_be = (const float*)d_in[8];
    const float* qW = (const float*)d_in[9];
    const float* qb = (const float*)d_in[10];
    const float* kW = (const float*)d_in[11];
    const float* kb = (const float*)d_in[12];
    const float* vW = (const float*)d_in[13];
    const float* vb = (const float*)d_in[14];
    const float* m1W = (const float*)d_in[15];
    const float* m1b = (const float*)d_in[16];
    const float* m1g = (const float*)d_in[17];
    const float* m1be = (const float*)d_in[18];
    const float* m2W = (const float*)d_in[19];
    const float* m2b = (const float*)d_in[20];
    const float* m2g = (const float*)d_in[21];
    const float* m2be = (const float*)d_in[22];
    const float* m3W = (const float*)d_in[23];
    const float* m3b = (const float*)d_in[24];
    const float* c1W = (const float*)d_in[25];
    const float* c1b = (const float*)d_in[26];
    const float* c2W = (const float*)d_in[27];
    const float* c2b = (const float*)d_in[28];
    const float* c3W = (const float*)d_in[29];
    const float* c3b = (const float*)d_in[30];
    float* out = (float*)d_out;

    float *x, *tmp, *q, *k, *v, *msg, *h1, *h2, *ss, *ss2, *S;
    float *rmaxp, *lhi, *llo, *rinv, *opart;
    cudaGetSymbolAddress((void**)&x, g_x);
    cudaGetSymbolAddress((void**)&tmp, g_tmp);
    cudaGetSymbolAddress((void**)&q, g_q);
    cudaGetSymbolAddress((void**)&k, g_k);
    cudaGetSymbolAddress((void**)&v, g_v);
    cudaGetSymbolAddress((void**)&msg, g_msg);
    cudaGetSymbolAddress((void**)&h1, g_h1);
    cudaGetSymbolAddress((void**)&h2, g_h2);
    cudaGetSymbolAddress((void**)&ss, g_ss);
    cudaGetSymbolAddress((void**)&ss2, g_ss2);
    cudaGetSymbolAddress((void**)&S, g_S);
    cudaGetSymbolAddress((void**)&rmaxp, g_rmaxp);
    cudaGetSymbolAddress((void**)&lhi, g_lhi);
    cudaGetSymbolAddress((void**)&llo, g_llo);
    cudaGetSymbolAddress((void**)&rinv, g_rinv);
    cudaGetSymbolAddress((void**)&opart, g_opart);

    size_t smem1 = (size_t)(128 * 128 + 128 * 64 + 128 * 6 + 64 * 6) * sizeof(float);
    size_t smem3 = (size_t)(128 * 64 + 64 * 68) * sizeof(float);
    cudaFuncSetAttribute(attn_logits_kernel, cudaFuncAttributeMaxDynamicSharedMemorySize,
                         (int)smem1);
    cudaFuncSetAttribute(attn_pv_kernel, cudaFuncAttributeMaxDynamicSharedMemorySize,
                         (int)smem3);

    const int EW = (FEAT_SZ + 255) / 256;
    dim3 cg128(47, 2, BB);
    dim3 cg64(47, 1, BB);
    dim3 cg3(47, 6, BB);
    dim3 lg(24, BB, JSPLIT);
    dim3 ag(47, BB, JSPLIT);

    init_embed_kernel<<<EW, 256>>>(corr, init_W, init_b, x);

    for (int i = 0; i < NLAYERS; i++) {
        conv_kernel<<<cg128, 256>>>(x, pcn_W + i * 128 * 128, pcn_b + i * 128, tmp,
                                    nullptr, 0, 128, 128);
        bn_stats_kernel<<<128, 256>>>(tmp, pcn_g + i * 128, pcn_be + i * 128, ss, 128);
        conv3_kernel<<<cg3, 256>>>(tmp,
                                   qW + i * 16384, kW + i * 16384, vW + i * 16384,
                                   qb + i * 128, kb + i * 128, vb + i * 128,
                                   q, k, v, ss);
        attn_logits_kernel<<<lg, 256, smem1>>>(q, k, src, tgt, S, rmaxp);
        attn_pv_kernel<<<ag, 256, smem3>>>(v, S, rmaxp, opart, lhi, llo);
        rinv_kernel<<<(BB * NPAD + 255) / 256, 256>>>(lhi, llo, rinv);
        conv_m1_kernel<<<cg64, 256>>>(opart, rinv, m1W + i * 64 * 128, m1b + i * 64, h1);
        bn_stats_kernel<<<64, 256>>>(h1, m1g + i * 64, m1be + i * 64, ss2, 64);
        conv_kernel<<<cg64, 256>>>(h1, m2W + i * 64 * 64, m2b + i * 64, h2, ss2, 1, 64, 64);
        bn_stats_kernel<<<64, 256>>>(h2, m2g + i * 64, m2be + i * 64, ss2, 64);
        conv_kernel<<<cg128, 256>>>(h2, m3W + i * 128 * 64, m3b + i * 128, msg, ss2, 1, 128, 64);
        bn_add_kernel<<<EW, 256>>>(tmp, ss, msg, x);
    }

    conv_kernel<<<cg64, 256>>>(x, c1W, c1b, h1, nullptr, 0, 32, 128);
    conv_kernel<<<cg64, 256>>>(h1, c2W, c2b, h2, nullptr, 1, 32, 32);
    conf_kernel<<<(BB * NPT + 255) / 256, 256>>>(h2, c3W, c3b, out);
    norm_kernel<<<(BB * NPT + 255) / 256, 256>>>(x, out + BB * NPT);
}